// round 1
// baseline (speedup 1.0000x reference)
#include <cuda_runtime.h>
#include <cuda_bf16.h>

// Problem constants
#define BB   4
#define LL   2048
#define DM   1024
#define DI   2048
#define NM   (BB*LL)      // 8192 tokens
#define XZW  4096         // 2*DI
#define PRW  96           // dt_rank + 2*d_state
#define DTR  64
#define DS   16

// ---------------- scratch (device globals; allocation-free rule) -------------
__device__ float g_xn[(size_t)NM*DM];
__device__ float g_xz[2][(size_t)NM*XZW];
__device__ float g_xc[2][(size_t)NM*DI];
__device__ float g_proj[2][(size_t)NM*PRW];
__device__ float g_delta[2][(size_t)NM*DI];
__device__ float g_yg[2][(size_t)NM*DI];
__device__ float g_ycat[(size_t)NM*DI];   // concat of per-dir out-proj results

// ---------------- LayerNorm --------------------------------------------------
__global__ __launch_bounds__(256) void ln_kernel(
    const float* __restrict__ x, const float* __restrict__ gw,
    const float* __restrict__ bw, float* __restrict__ xn)
{
    __shared__ float red[16];
    int m = blockIdx.x, tid = threadIdx.x;
    const float4* xr = (const float4*)(x + (size_t)m*DM);
    float4 v = xr[tid];
    float s  = v.x+v.y+v.z+v.w;
    float ss = v.x*v.x+v.y*v.y+v.z*v.z+v.w*v.w;
    #pragma unroll
    for (int o=16;o;o>>=1){ s += __shfl_xor_sync(~0u,s,o); ss += __shfl_xor_sync(~0u,ss,o); }
    if ((tid&31)==0){ red[tid>>5]=s; red[8+(tid>>5)]=ss; }
    __syncthreads();
    if (tid<32){
        float a  = (tid<8)? red[tid]   : 0.f;
        float b2 = (tid<8)? red[8+tid] : 0.f;
        #pragma unroll
        for (int o=4;o;o>>=1){ a += __shfl_xor_sync(~0u,a,o); b2 += __shfl_xor_sync(~0u,b2,o); }
        if (tid==0){ red[0]=a; red[8]=b2; }
    }
    __syncthreads();
    float mu   = red[0]*(1.0f/DM);
    float var  = red[8]*(1.0f/DM) - mu*mu;
    float rstd = rsqrtf(var + 1e-5f);
    float4 g4 = ((const float4*)gw)[tid];
    float4 b4 = ((const float4*)bw)[tid];
    float4 o;
    o.x = (v.x-mu)*rstd*g4.x + b4.x;
    o.y = (v.y-mu)*rstd*g4.y + b4.y;
    o.z = (v.z-mu)*rstd*g4.z + b4.z;
    o.w = (v.w-mu)*rstd*g4.w + b4.w;
    ((float4*)(xn + (size_t)m*DM))[tid] = o;
}

// ---------------- Tiled fp32 SGEMM, NT form: C[m,n] = sum_k A[m,k]*B[n,k] ----
// EPI: 0 = none, 1 = softplus(acc+bias), 2 = acc + bias + resid
template<int EPI>
__global__ __launch_bounds__(256) void sgemm_nt(
    const float* __restrict__ A, const float* __restrict__ B, float* __restrict__ C,
    int M, int N, int K, int lda, int ldb, int ldc,
    const float* __restrict__ bias, const float* __restrict__ resid)
{
    __shared__ float As[8][128];
    __shared__ float Bs[8][128];
    int tid = threadIdx.x;
    int m0 = blockIdx.y*128, n0 = blockIdx.x*128;
    int tx = tid & 15, ty = tid >> 4;
    int lrow = tid >> 1;
    int lk = (tid & 1)*4;
    const float* Ap = A + (size_t)(m0+lrow)*lda + lk;
    const float* Bp = B + (size_t)(n0+lrow)*ldb + lk;
    float acc[8][8];
    #pragma unroll
    for (int i=0;i<8;i++)
        #pragma unroll
        for (int j=0;j<8;j++) acc[i][j]=0.f;

    for (int k0=0;k0<K;k0+=8) {
        float4 av = *(const float4*)(Ap + k0);
        float4 bv = *(const float4*)(Bp + k0);
        __syncthreads();
        As[lk  ][lrow]=av.x; As[lk+1][lrow]=av.y; As[lk+2][lrow]=av.z; As[lk+3][lrow]=av.w;
        Bs[lk  ][lrow]=bv.x; Bs[lk+1][lrow]=bv.y; Bs[lk+2][lrow]=bv.z; Bs[lk+3][lrow]=bv.w;
        __syncthreads();
        #pragma unroll
        for (int kk=0;kk<8;kk++){
            float ra[8], rb[8];
            *(float4*)(ra)   = *(const float4*)&As[kk][ty*8];
            *(float4*)(ra+4) = *(const float4*)&As[kk][ty*8+4];
            *(float4*)(rb)   = *(const float4*)&Bs[kk][tx*8];
            *(float4*)(rb+4) = *(const float4*)&Bs[kk][tx*8+4];
            #pragma unroll
            for (int i=0;i<8;i++)
                #pragma unroll
                for (int j=0;j<8;j++) acc[i][j] = fmaf(ra[i], rb[j], acc[i][j]);
        }
    }

    #pragma unroll
    for (int i=0;i<8;i++){
        int m = m0 + ty*8 + i;
        #pragma unroll
        for (int j0=0;j0<8;j0+=4){
            int n = n0 + tx*8 + j0;
            float4 ov;
            float* pv = (float*)&ov;
            #pragma unroll
            for (int j=0;j<4;j++){
                float v = acc[i][j0+j];
                if (EPI==1){
                    v += bias[n+j];
                    v = (v > 20.f) ? v : log1pf(expf(v));
                }
                if (EPI==2){
                    v += bias[n+j] + resid[(size_t)m*ldc + n + j];
                }
                pv[j] = v;
            }
            *(float4*)(C + (size_t)m*ldc + n) = ov;
        }
    }
}

// ---------------- Depthwise causal / anti-causal conv + bias + SiLU ----------
__global__ __launch_bounds__(256) void conv_silu_kernel(
    const float* __restrict__ xz, const float* __restrict__ cw,
    const float* __restrict__ cb, float* __restrict__ xc, int reverse)
{
    int d = blockIdx.x*256 + threadIdx.x;   // 0..2047
    int t = blockIdx.y;                     // 0..2047
    int b = blockIdx.z;                     // 0..3
    float w0 = cw[d*4+0], w1 = cw[d*4+1], w2 = cw[d*4+2], w3 = cw[d*4+3];
    float acc = cb[d];
    size_t rowb = (size_t)b*LL;
    if (!reverse){
        // causal: acc += sum_k w[k]*x[t-3+k]
        if (t-3 >= 0) acc += w0 * xz[(rowb + t-3)*XZW + d];
        if (t-2 >= 0) acc += w1 * xz[(rowb + t-2)*XZW + d];
        if (t-1 >= 0) acc += w2 * xz[(rowb + t-1)*XZW + d];
        acc += w3 * xz[(rowb + t)*XZW + d];
    } else {
        // flipped-causal == anti-causal with reversed taps: sum_j w[3-j]*x[t+j]
        acc += w3 * xz[(rowb + t)*XZW + d];
        if (t+1 < LL) acc += w2 * xz[(rowb + t+1)*XZW + d];
        if (t+2 < LL) acc += w1 * xz[(rowb + t+2)*XZW + d];
        if (t+3 < LL) acc += w0 * xz[(rowb + t+3)*XZW + d];
    }
    float s = acc / (1.f + expf(-acc));     // SiLU
    xc[((size_t)b*LL + t)*DI + d] = s;
}

// ---------------- x-proj (small-N GEMM: N=96, K=2048), 4 rows per block ------
__global__ __launch_bounds__(256) void xproj_kernel(
    const float* __restrict__ xc, const float* __restrict__ w, float* __restrict__ proj)
{
    __shared__ float sx[4][DI];
    int m0 = blockIdx.x * 4;
    int tid = threadIdx.x;
    const float4* src = (const float4*)(xc + (size_t)m0*DI);
    float4* dst = (float4*)sx;
    #pragma unroll
    for (int i = tid; i < 4*(DI/4); i += 256) dst[i] = src[i];
    __syncthreads();
    int warp = tid >> 5, lane = tid & 31;
    for (int j = warp; j < PRW; j += 8) {
        const float* wr = w + (size_t)j*DI;
        float a0=0.f, a1=0.f, a2=0.f, a3=0.f;
        for (int k = lane; k < DI; k += 32) {
            float wv = wr[k];
            a0 = fmaf(wv, sx[0][k], a0);
            a1 = fmaf(wv, sx[1][k], a1);
            a2 = fmaf(wv, sx[2][k], a2);
            a3 = fmaf(wv, sx[3][k], a3);
        }
        #pragma unroll
        for (int o=16;o;o>>=1){
            a0 += __shfl_xor_sync(~0u,a0,o);
            a1 += __shfl_xor_sync(~0u,a1,o);
            a2 += __shfl_xor_sync(~0u,a2,o);
            a3 += __shfl_xor_sync(~0u,a3,o);
        }
        if (lane==0){
            proj[(size_t)(m0+0)*PRW + j] = a0;
            proj[(size_t)(m0+1)*PRW + j] = a1;
            proj[(size_t)(m0+2)*PRW + j] = a2;
            proj[(size_t)(m0+3)*PRW + j] = a3;
        }
    }
}

// ---------------- FMA-only exp2 (avoids MUFU bottleneck in the scan) ---------
__device__ __forceinline__ float exp2p(float x){
    x = fmaxf(x, -126.f);
    float fl = floorf(x);
    float f = x - fl;
    float p = 1.5400277e-4f;
    p = fmaf(p, f, 1.3335581e-3f);
    p = fmaf(p, f, 9.6181290e-3f);
    p = fmaf(p, f, 5.5504110e-2f);
    p = fmaf(p, f, 2.4022651e-1f);
    p = fmaf(p, f, 6.9314718e-1f);
    p = fmaf(p, f, 1.0f);
    return p * __int_as_float(((int)fl + 127) << 23);
}

// ---------------- Selective scan + D-skip + SiLU(z) gate ---------------------
// 4 threads per channel, 4 states each; block = 128 thr = 32 channels.
__global__ __launch_bounds__(128) void scan_kernel(
    const float* __restrict__ delta, const float* __restrict__ xc,
    const float* __restrict__ proj,  const float* __restrict__ xz,
    const float* __restrict__ A_log, const float* __restrict__ Dw,
    float* __restrict__ yg, int reverse)
{
    __shared__ float sBC[32];
    int tid = threadIdx.x;
    int chl = tid >> 2;          // 0..31
    int sg  = tid & 3;           // 0..3
    int d = blockIdx.x*32 + chl;
    int b = blockIdx.y;
    const float LOG2E = 1.4426950408889634f;
    float c[4], h[4];
    #pragma unroll
    for (int i=0;i<4;i++){
        c[i] = -expf(A_log[(size_t)d*DS + sg*4 + i]) * LOG2E;
        h[i] = 0.f;
    }
    float Dv = Dw[d];
    size_t rowb = (size_t)b*LL;
    for (int step = 0; step < LL; step++){
        int t = reverse ? (LL-1-step) : step;
        size_t m = rowb + t;
        __syncthreads();
        if (tid < 32) sBC[tid] = proj[m*PRW + DTR + tid];
        __syncthreads();
        float dlt = delta[m*DI + d];
        float xv  = xc[m*DI + d];
        float dx  = dlt * xv;
        float y = 0.f;
        #pragma unroll
        for (int i=0;i<4;i++){
            float e = exp2p(dlt * c[i]);
            h[i] = fmaf(e, h[i], dx * sBC[sg*4+i]);
            y = fmaf(h[i], sBC[16 + sg*4+i], y);
        }
        y += __shfl_xor_sync(~0u, y, 1);
        y += __shfl_xor_sync(~0u, y, 2);
        if (sg == 0){
            float z  = xz[m*XZW + DI + d];
            float sz = z / (1.f + expf(-z));
            yg[m*DI + d] = (y + xv*Dv) * sz;
        }
    }
}

// ---------------- Host launcher ---------------------------------------------
extern "C" void kernel_launch(void* const* d_in, const int* in_sizes, int n_in,
                              void* d_out, int out_size)
{
    const float* X       = (const float*)d_in[0];
    const float* ln_g    = (const float*)d_in[1];
    const float* ln_b    = (const float*)d_in[2];
    const float* merge_w = (const float*)d_in[3];
    const float* merge_b = (const float*)d_in[4];

    float *xn_p, *xz_p, *xc_p, *proj_p, *delta_p, *yg_p, *ycat_p;
    cudaGetSymbolAddress((void**)&xn_p,   g_xn);
    cudaGetSymbolAddress((void**)&xz_p,   g_xz);
    cudaGetSymbolAddress((void**)&xc_p,   g_xc);
    cudaGetSymbolAddress((void**)&proj_p, g_proj);
    cudaGetSymbolAddress((void**)&delta_p,g_delta);
    cudaGetSymbolAddress((void**)&yg_p,   g_yg);
    cudaGetSymbolAddress((void**)&ycat_p, g_ycat);

    // 1. LayerNorm
    ln_kernel<<<NM, 256>>>(X, ln_g, ln_b, xn_p);

    for (int dir = 0; dir < 2; dir++){
        int base = 5 + dir*9;
        const float* in_w    = (const float*)d_in[base+0];
        const float* conv_w  = (const float*)d_in[base+1];
        const float* conv_b  = (const float*)d_in[base+2];
        const float* xproj_w = (const float*)d_in[base+3];
        const float* dt_w    = (const float*)d_in[base+4];
        const float* dt_b    = (const float*)d_in[base+5];
        const float* A_log   = (const float*)d_in[base+6];
        const float* Dw      = (const float*)d_in[base+7];
        const float* out_w   = (const float*)d_in[base+8];

        float* xz_d    = xz_p    + (size_t)dir*NM*XZW;
        float* xc_d    = xc_p    + (size_t)dir*NM*DI;
        float* proj_d  = proj_p  + (size_t)dir*NM*PRW;
        float* delta_d = delta_p + (size_t)dir*NM*DI;
        float* yg_d    = yg_p    + (size_t)dir*NM*DI;

        // 2. in-proj: xz = xn @ in_w.T   [8192,4096] K=1024
        sgemm_nt<0><<<dim3(XZW/128, NM/128), 256>>>(
            xn_p, in_w, xz_d, NM, XZW, DM, DM, DM, XZW, nullptr, nullptr);

        // 3. depthwise conv + SiLU
        conv_silu_kernel<<<dim3(DI/256, LL, BB), 256>>>(xz_d, conv_w, conv_b, xc_d, dir);

        // 4. x-proj: [8192,96] K=2048
        xproj_kernel<<<NM/4, 256>>>(xc_d, xproj_w, proj_d);

        // 5. delta = softplus(dt @ dt_w.T + dt_b)  [8192,2048] K=64, lda=96
        sgemm_nt<1><<<dim3(DI/128, NM/128), 256>>>(
            proj_d, dt_w, delta_d, NM, DI, DTR, PRW, DTR, DI, dt_b, nullptr);

        // 6. selective scan + gate
        scan_kernel<<<dim3(DI/32, BB), 128>>>(
            delta_d, xc_d, proj_d, xz_d, A_log, Dw, yg_d, dir);

        // 7. out-proj into concat buffer: [8192,1024] K=2048, col offset dir*1024
        sgemm_nt<0><<<dim3(DM/128, NM/128), 256>>>(
            yg_d, out_w, ycat_p + (size_t)dir*DM, NM, DM, DI, DI, DI, DI, nullptr, nullptr);
    }

    // 8. merge + bias + residual: out = x + ycat @ merge_w.T + merge_b
    sgemm_nt<2><<<dim3(DM/128, NM/128), 256>>>(
        ycat_p, merge_w, (float*)d_out, NM, DM, DI, DI, DI, DM, merge_b, X);
}

// round 3
// speedup vs baseline: 1.9585x; 1.9585x over previous
#include <cuda_runtime.h>
#include <cuda_bf16.h>
#include <cstdint>

// Problem constants
#define BB   4
#define LL   2048
#define DM   1024
#define DI   2048
#define NM   (BB*LL)      // 8192 tokens
#define XZW  4096         // 2*DI
#define PRW  96           // dt_rank + 2*d_state
#define DTR  64
#define DS   16

// ---------------- scratch (device globals; allocation-free rule) -------------
__device__ float g_xn[(size_t)NM*DM];
__device__ float g_xz[2][(size_t)NM*XZW];
__device__ float g_xc[2][(size_t)NM*DI];
__device__ float g_proj[2][(size_t)NM*PRW];
__device__ float g_delta[2][(size_t)NM*DI];
__device__ float g_yg[2][(size_t)NM*DI];
__device__ float g_ycat[(size_t)NM*DI];

// ---------------- LayerNorm --------------------------------------------------
__global__ __launch_bounds__(256) void ln_kernel(
    const float* __restrict__ x, const float* __restrict__ gw,
    const float* __restrict__ bw, float* __restrict__ xn)
{
    __shared__ float red[16];
    int m = blockIdx.x, tid = threadIdx.x;
    const float4* xr = (const float4*)(x + (size_t)m*DM);
    float4 v = xr[tid];
    float s  = v.x+v.y+v.z+v.w;
    float ss = v.x*v.x+v.y*v.y+v.z*v.z+v.w*v.w;
    #pragma unroll
    for (int o=16;o;o>>=1){ s += __shfl_xor_sync(~0u,s,o); ss += __shfl_xor_sync(~0u,ss,o); }
    if ((tid&31)==0){ red[tid>>5]=s; red[8+(tid>>5)]=ss; }
    __syncthreads();
    if (tid<32){
        float a  = (tid<8)? red[tid]   : 0.f;
        float b2 = (tid<8)? red[8+tid] : 0.f;
        #pragma unroll
        for (int o=4;o;o>>=1){ a += __shfl_xor_sync(~0u,a,o); b2 += __shfl_xor_sync(~0u,b2,o); }
        if (tid==0){ red[0]=a; red[8]=b2; }
    }
    __syncthreads();
    float mu   = red[0]*(1.0f/DM);
    float var  = red[8]*(1.0f/DM) - mu*mu;
    float rstd = rsqrtf(var + 1e-5f);
    float4 g4 = ((const float4*)gw)[tid];
    float4 b4 = ((const float4*)bw)[tid];
    float4 o;
    o.x = (v.x-mu)*rstd*g4.x + b4.x;
    o.y = (v.y-mu)*rstd*g4.y + b4.y;
    o.z = (v.z-mu)*rstd*g4.z + b4.z;
    o.w = (v.w-mu)*rstd*g4.w + b4.w;
    ((float4*)(xn + (size_t)m*DM))[tid] = o;
}

// ---------------- TF32 tensor-core GEMM, NT: C[m,n] = sum_k A[m,k]*B[n,k] ----
// 128x128x32 tile, 8 warps (4x2), warp tile 32x64, m16n8k8 tf32 mma.
// EPI: 0 = none, 1 = softplus(acc+bias), 2 = acc + bias + resid
#define BKk 32
#define SMPAD 136   // 128 + 8 pad -> conflict-free fragment LDS

__device__ __forceinline__ uint32_t f2tf32(float x){
    uint32_t o;
    asm volatile("cvt.rna.tf32.f32 %0, %1;" : "=r"(o) : "f"(x));
    return o;
}

template<int EPI>
__global__ __launch_bounds__(256) void sgemm_tc(
    const float* __restrict__ A, const float* __restrict__ B, float* __restrict__ C,
    int M, int N, int K, int lda, int ldb, int ldc,
    const float* __restrict__ bias, const float* __restrict__ resid)
{
    __shared__ uint32_t As[BKk][SMPAD];
    __shared__ uint32_t Bs[BKk][SMPAD];

    int tid  = threadIdx.x;
    int warp = tid >> 5, lane = tid & 31;
    int gid  = lane >> 2, tig = lane & 3;     // mma group / thread-in-group
    int wm   = (warp >> 1) * 32;              // warp m offset in tile
    int wn   = (warp & 1) * 64;               // warp n offset in tile
    int m0 = blockIdx.y * 128, n0 = blockIdx.x * 128;

    // gmem->reg staging: 4 float4 per matrix per thread per chunk
    // slot s (0..1023): row = s>>3, kq = (s&7)*4
    int srow[4], skq[4];
    #pragma unroll
    for (int i=0;i<4;i++){ int s = tid + i*256; srow[i] = s>>3; skq[i] = (s&7)*4; }

    float4 va[4], vb[4];
    auto load_regs = [&](int k0){
        #pragma unroll
        for (int i=0;i<4;i++){
            va[i] = *(const float4*)(A + (size_t)(m0+srow[i])*lda + k0 + skq[i]);
            int nrow = n0 + srow[i];
            if (nrow < N)
                vb[i] = *(const float4*)(B + (size_t)nrow*ldb + k0 + skq[i]);
            else
                vb[i] = make_float4(0.f,0.f,0.f,0.f);
        }
    };
    auto store_smem = [&](){
        #pragma unroll
        for (int i=0;i<4;i++){
            As[skq[i]  ][srow[i]] = f2tf32(va[i].x);
            As[skq[i]+1][srow[i]] = f2tf32(va[i].y);
            As[skq[i]+2][srow[i]] = f2tf32(va[i].z);
            As[skq[i]+3][srow[i]] = f2tf32(va[i].w);
            Bs[skq[i]  ][srow[i]] = f2tf32(vb[i].x);
            Bs[skq[i]+1][srow[i]] = f2tf32(vb[i].y);
            Bs[skq[i]+2][srow[i]] = f2tf32(vb[i].z);
            Bs[skq[i]+3][srow[i]] = f2tf32(vb[i].w);
        }
    };

    float acc[2][8][4];
    #pragma unroll
    for (int mt=0;mt<2;mt++)
        #pragma unroll
        for (int nt=0;nt<8;nt++)
            #pragma unroll
            for (int r=0;r<4;r++) acc[mt][nt][r]=0.f;

    int nchunk = K / BKk;
    load_regs(0);
    store_smem();
    __syncthreads();

    for (int ck=0; ck<nchunk; ck++){
        if (ck+1 < nchunk) load_regs((ck+1)*BKk);

        #pragma unroll
        for (int ks=0; ks<BKk/8; ks++){
            int kk = ks*8;
            uint32_t af[2][4];
            #pragma unroll
            for (int mt=0;mt<2;mt++){
                int r = wm + mt*16 + gid;
                af[mt][0] = As[kk+tig  ][r];
                af[mt][1] = As[kk+tig  ][r+8];
                af[mt][2] = As[kk+tig+4][r];
                af[mt][3] = As[kk+tig+4][r+8];
            }
            uint32_t bf[8][2];
            #pragma unroll
            for (int nt=0;nt<8;nt++){
                int c = wn + nt*8 + gid;
                bf[nt][0] = Bs[kk+tig  ][c];
                bf[nt][1] = Bs[kk+tig+4][c];
            }
            #pragma unroll
            for (int mt=0;mt<2;mt++)
                #pragma unroll
                for (int nt=0;nt<8;nt++){
                    asm volatile(
                        "mma.sync.aligned.m16n8k8.row.col.f32.tf32.tf32.f32 "
                        "{%0,%1,%2,%3}, {%4,%5,%6,%7}, {%8,%9}, {%0,%1,%2,%3};\n"
                        : "+f"(acc[mt][nt][0]), "+f"(acc[mt][nt][1]),
                          "+f"(acc[mt][nt][2]), "+f"(acc[mt][nt][3])
                        : "r"(af[mt][0]), "r"(af[mt][1]), "r"(af[mt][2]), "r"(af[mt][3]),
                          "r"(bf[nt][0]), "r"(bf[nt][1]));
                }
        }

        if (ck+1 < nchunk){
            __syncthreads();
            store_smem();
            __syncthreads();
        }
    }

    // Epilogue: acc[mt][nt]: rows (gid, gid+8), cols (tig*2, tig*2+1)
    #pragma unroll
    for (int mt=0;mt<2;mt++){
        int r0 = m0 + wm + mt*16 + gid;
        #pragma unroll
        for (int nt=0;nt<8;nt++){
            int c = n0 + wn + nt*8 + tig*2;
            if (c >= N) continue;
            float v[4];
            #pragma unroll
            for (int q=0;q<4;q++) v[q] = acc[mt][nt][q];
            if (EPI==1){
                #pragma unroll
                for (int q=0;q<4;q++){
                    float t = v[q] + bias[c + (q&1)];
                    v[q] = (t > 20.f) ? t : log1pf(expf(t));
                }
            }
            if (EPI==2){
                v[0] += bias[c]   + resid[(size_t)r0*ldc + c];
                v[1] += bias[c+1] + resid[(size_t)r0*ldc + c+1];
                v[2] += bias[c]   + resid[(size_t)(r0+8)*ldc + c];
                v[3] += bias[c+1] + resid[(size_t)(r0+8)*ldc + c+1];
            }
            *(float2*)(C + (size_t)r0*ldc + c)     = make_float2(v[0], v[1]);
            *(float2*)(C + (size_t)(r0+8)*ldc + c) = make_float2(v[2], v[3]);
        }
    }
}

// ---------------- Depthwise causal / anti-causal conv + bias + SiLU ----------
__global__ __launch_bounds__(256) void conv_silu_kernel(
    const float* __restrict__ xz, const float* __restrict__ cw,
    const float* __restrict__ cb, float* __restrict__ xc, int reverse)
{
    int d = blockIdx.x*256 + threadIdx.x;
    int t = blockIdx.y;
    int b = blockIdx.z;
    float w0 = cw[d*4+0], w1 = cw[d*4+1], w2 = cw[d*4+2], w3 = cw[d*4+3];
    float acc = cb[d];
    size_t rowb = (size_t)b*LL;
    if (!reverse){
        if (t-3 >= 0) acc += w0 * xz[(rowb + t-3)*XZW + d];
        if (t-2 >= 0) acc += w1 * xz[(rowb + t-2)*XZW + d];
        if (t-1 >= 0) acc += w2 * xz[(rowb + t-1)*XZW + d];
        acc += w3 * xz[(rowb + t)*XZW + d];
    } else {
        acc += w3 * xz[(rowb + t)*XZW + d];
        if (t+1 < LL) acc += w2 * xz[(rowb + t+1)*XZW + d];
        if (t+2 < LL) acc += w1 * xz[(rowb + t+2)*XZW + d];
        if (t+3 < LL) acc += w0 * xz[(rowb + t+3)*XZW + d];
    }
    float s = acc / (1.f + expf(-acc));
    xc[((size_t)b*LL + t)*DI + d] = s;
}

// ---------------- FMA-only exp2 ----------------------------------------------
__device__ __forceinline__ float exp2p(float x){
    x = fmaxf(x, -126.f);
    float fl = floorf(x);
    float f = x - fl;
    float p = 1.5400277e-4f;
    p = fmaf(p, f, 1.3335581e-3f);
    p = fmaf(p, f, 9.6181290e-3f);
    p = fmaf(p, f, 5.5504110e-2f);
    p = fmaf(p, f, 2.4022651e-1f);
    p = fmaf(p, f, 6.9314718e-1f);
    p = fmaf(p, f, 1.0f);
    return p * __int_as_float(((int)fl + 127) << 23);
}

// ---------------- Selective scan + D-skip + SiLU(z) gate ---------------------
__global__ __launch_bounds__(128) void scan_kernel(
    const float* __restrict__ delta, const float* __restrict__ xc,
    const float* __restrict__ proj,  const float* __restrict__ xz,
    const float* __restrict__ A_log, const float* __restrict__ Dw,
    float* __restrict__ yg, int reverse)
{
    __shared__ float sBC[32];
    int tid = threadIdx.x;
    int chl = tid >> 2;
    int sg  = tid & 3;
    int d = blockIdx.x*32 + chl;
    int b = blockIdx.y;
    const float LOG2E = 1.4426950408889634f;
    float c[4], h[4];
    #pragma unroll
    for (int i=0;i<4;i++){
        c[i] = -expf(A_log[(size_t)d*DS + sg*4 + i]) * LOG2E;
        h[i] = 0.f;
    }
    float Dv = Dw[d];
    size_t rowb = (size_t)b*LL;
    for (int step = 0; step < LL; step++){
        int t = reverse ? (LL-1-step) : step;
        size_t m = rowb + t;
        __syncthreads();
        if (tid < 32) sBC[tid] = proj[m*PRW + DTR + tid];
        __syncthreads();
        float dlt = delta[m*DI + d];
        float xv  = xc[m*DI + d];
        float dx  = dlt * xv;
        float y = 0.f;
        #pragma unroll
        for (int i=0;i<4;i++){
            float e = exp2p(dlt * c[i]);
            h[i] = fmaf(e, h[i], dx * sBC[sg*4+i]);
            y = fmaf(h[i], sBC[16 + sg*4+i], y);
        }
        y += __shfl_xor_sync(~0u, y, 1);
        y += __shfl_xor_sync(~0u, y, 2);
        if (sg == 0){
            float z  = xz[m*XZW + DI + d];
            float sz = z / (1.f + expf(-z));
            yg[m*DI + d] = (y + xv*Dv) * sz;
        }
    }
}

// ---------------- Host launcher ---------------------------------------------
extern "C" void kernel_launch(void* const* d_in, const int* in_sizes, int n_in,
                              void* d_out, int out_size)
{
    const float* X       = (const float*)d_in[0];
    const float* ln_g    = (const float*)d_in[1];
    const float* ln_b    = (const float*)d_in[2];
    const float* merge_w = (const float*)d_in[3];
    const float* merge_b = (const float*)d_in[4];

    float *xn_p, *xz_p, *xc_p, *proj_p, *delta_p, *yg_p, *ycat_p;
    cudaGetSymbolAddress((void**)&xn_p,   g_xn);
    cudaGetSymbolAddress((void**)&xz_p,   g_xz);
    cudaGetSymbolAddress((void**)&xc_p,   g_xc);
    cudaGetSymbolAddress((void**)&proj_p, g_proj);
    cudaGetSymbolAddress((void**)&delta_p,g_delta);
    cudaGetSymbolAddress((void**)&yg_p,   g_yg);
    cudaGetSymbolAddress((void**)&ycat_p, g_ycat);

    // 1. LayerNorm
    ln_kernel<<<NM, 256>>>(X, ln_g, ln_b, xn_p);

    for (int dir = 0; dir < 2; dir++){
        int base = 5 + dir*9;
        const float* in_w    = (const float*)d_in[base+0];
        const float* conv_w  = (const float*)d_in[base+1];
        const float* conv_b  = (const float*)d_in[base+2];
        const float* xproj_w = (const float*)d_in[base+3];
        const float* dt_w    = (const float*)d_in[base+4];
        const float* dt_b    = (const float*)d_in[base+5];
        const float* A_log   = (const float*)d_in[base+6];
        const float* Dw      = (const float*)d_in[base+7];
        const float* out_w   = (const float*)d_in[base+8];

        float* xz_d    = xz_p    + (size_t)dir*NM*XZW;
        float* xc_d    = xc_p    + (size_t)dir*NM*DI;
        float* proj_d  = proj_p  + (size_t)dir*NM*PRW;
        float* delta_d = delta_p + (size_t)dir*NM*DI;
        float* yg_d    = yg_p    + (size_t)dir*NM*DI;

        // 2. in-proj: xz = xn @ in_w.T   [8192,4096] K=1024
        sgemm_tc<0><<<dim3(XZW/128, NM/128), 256>>>(
            xn_p, in_w, xz_d, NM, XZW, DM, DM, DM, XZW, nullptr, nullptr);

        // 3. depthwise conv + SiLU
        conv_silu_kernel<<<dim3(DI/256, LL, BB), 256>>>(xz_d, conv_w, conv_b, xc_d, dir);

        // 4. x-proj: [8192,96] K=2048 (N-guarded tensor-core GEMM)
        sgemm_tc<0><<<dim3(1, NM/128), 256>>>(
            xc_d, xproj_w, proj_d, NM, PRW, DI, DI, DI, PRW, nullptr, nullptr);

        // 5. delta = softplus(dt @ dt_w.T + dt_b)  [8192,2048] K=64, lda=96
        sgemm_tc<1><<<dim3(DI/128, NM/128), 256>>>(
            proj_d, dt_w, delta_d, NM, DI, DTR, PRW, DTR, DI, dt_b, nullptr);

        // 6. selective scan + gate
        scan_kernel<<<dim3(DI/32, BB), 128>>>(
            delta_d, xc_d, proj_d, xz_d, A_log, Dw, yg_d, dir);

        // 7. out-proj into concat buffer: [8192,1024] K=2048
        sgemm_tc<0><<<dim3(DM/128, NM/128), 256>>>(
            yg_d, out_w, ycat_p + (size_t)dir*DM, NM, DM, DI, DI, DI, DI, nullptr, nullptr);
    }

    // 8. merge + bias + residual: out = x + ycat @ merge_w.T + merge_b
    sgemm_tc<2><<<dim3(DM/128, NM/128), 256>>>(
        ycat_p, merge_w, (float*)d_out, NM, DM, DI, DI, DI, DM, merge_b, X);
}

// round 4
// speedup vs baseline: 4.9240x; 2.5142x over previous
#include <cuda_runtime.h>
#include <cuda_bf16.h>
#include <cstdint>

// Problem constants
#define BB   4
#define LL   2048
#define DM   1024
#define DI   2048
#define NM   (BB*LL)      // 8192 tokens
#define XZW  4096         // 2*DI
#define PRW  96           // dt_rank + 2*d_state
#define DTR  64
#define DS   16

// ---------------- scratch (device globals; allocation-free rule) -------------
__device__ float g_xn[(size_t)NM*DM];
__device__ float g_xz[2][(size_t)NM*XZW];
__device__ float g_xc[2][(size_t)NM*DI];
__device__ float g_proj[2][(size_t)NM*PRW];
__device__ float g_delta[2][(size_t)NM*DI];
__device__ float g_yg[2][(size_t)NM*DI];
__device__ float g_ycat[(size_t)NM*DI];

// ---------------- LayerNorm --------------------------------------------------
__global__ __launch_bounds__(256) void ln_kernel(
    const float* __restrict__ x, const float* __restrict__ gw,
    const float* __restrict__ bw, float* __restrict__ xn)
{
    __shared__ float red[16];
    int m = blockIdx.x, tid = threadIdx.x;
    const float4* xr = (const float4*)(x + (size_t)m*DM);
    float4 v = xr[tid];
    float s  = v.x+v.y+v.z+v.w;
    float ss = v.x*v.x+v.y*v.y+v.z*v.z+v.w*v.w;
    #pragma unroll
    for (int o=16;o;o>>=1){ s += __shfl_xor_sync(~0u,s,o); ss += __shfl_xor_sync(~0u,ss,o); }
    if ((tid&31)==0){ red[tid>>5]=s; red[8+(tid>>5)]=ss; }
    __syncthreads();
    if (tid<32){
        float a  = (tid<8)? red[tid]   : 0.f;
        float b2 = (tid<8)? red[8+tid] : 0.f;
        #pragma unroll
        for (int o=4;o;o>>=1){ a += __shfl_xor_sync(~0u,a,o); b2 += __shfl_xor_sync(~0u,b2,o); }
        if (tid==0){ red[0]=a; red[8]=b2; }
    }
    __syncthreads();
    float mu   = red[0]*(1.0f/DM);
    float var  = red[8]*(1.0f/DM) - mu*mu;
    float rstd = rsqrtf(var + 1e-5f);
    float4 g4 = ((const float4*)gw)[tid];
    float4 b4 = ((const float4*)bw)[tid];
    float4 o;
    o.x = (v.x-mu)*rstd*g4.x + b4.x;
    o.y = (v.y-mu)*rstd*g4.y + b4.y;
    o.z = (v.z-mu)*rstd*g4.z + b4.z;
    o.w = (v.w-mu)*rstd*g4.w + b4.w;
    ((float4*)(xn + (size_t)m*DM))[tid] = o;
}

// ---------------- BF16 tensor-core GEMM, NT: C[m,n] = sum_k A[m,k]*B[n,k] ----
// 128x128x32 tile, 8 warps (4x2), warp tile 32x64, m16n8k16 bf16 mma,
// double-buffered smem, ldmatrix fragment loads, fp32 gmem converted at load.
// EPI: 0 = none, 1 = softplus(acc+bias), 2 = acc + bias + resid
#define BKk 32
#define SROW 20          // row stride in u32: 16 (32 bf16) + 4 pad (8 bf16)
#define BUFU32 (128*SROW)

__device__ __forceinline__ uint32_t pack_bf2(float x, float y){
    __nv_bfloat162 h = __float22bfloat162_rn(make_float2(x, y));
    return *(uint32_t*)&h;
}
__device__ __forceinline__ uint32_t smem_u32p(const void* p){
    return (uint32_t)__cvta_generic_to_shared(p);
}
__device__ __forceinline__ void ldsm4(uint32_t& r0, uint32_t& r1, uint32_t& r2, uint32_t& r3, uint32_t a){
    asm volatile("ldmatrix.sync.aligned.m8n8.x4.shared.b16 {%0,%1,%2,%3}, [%4];\n"
        : "=r"(r0), "=r"(r1), "=r"(r2), "=r"(r3) : "r"(a));
}

template<int EPI>
__global__ __launch_bounds__(256) void gemm_bf16(
    const float* __restrict__ A, const float* __restrict__ B, float* __restrict__ C,
    int M, int N, int K, int lda, int ldb, int ldc,
    const float* __restrict__ bias, const float* __restrict__ resid)
{
    __shared__ uint32_t As[2][BUFU32];
    __shared__ uint32_t Bs[2][BUFU32];

    int tid  = threadIdx.x;
    int warp = tid >> 5, lane = tid & 31;
    int gid  = lane >> 2, tig = lane & 3;
    int wm   = (warp >> 1) * 32;
    int wn   = (warp & 1) * 64;
    int m0 = blockIdx.y * 128, n0 = blockIdx.x * 128;

    // staging map: slot s (0..1023): row = s>>3, k-quad = (s&7)*4 (floats)
    int srow[4], skq[4];
    #pragma unroll
    for (int i=0;i<4;i++){ int s = tid + i*256; srow[i] = s>>3; skq[i] = (s&7)*4; }

    uint32_t ua[4][2], ub[4][2];
    auto load_regs = [&](int k0){
        #pragma unroll
        for (int i=0;i<4;i++){
            float4 v = *(const float4*)(A + (size_t)(m0+srow[i])*lda + k0 + skq[i]);
            ua[i][0] = pack_bf2(v.x, v.y);
            ua[i][1] = pack_bf2(v.z, v.w);
            int nrow = n0 + srow[i];
            float4 w = (nrow < N) ? *(const float4*)(B + (size_t)nrow*ldb + k0 + skq[i])
                                  : make_float4(0.f,0.f,0.f,0.f);
            ub[i][0] = pack_bf2(w.x, w.y);
            ub[i][1] = pack_bf2(w.z, w.w);
        }
    };
    auto store_smem = [&](int buf){
        #pragma unroll
        for (int i=0;i<4;i++){
            int off = srow[i]*SROW + (skq[i]>>1);
            *(uint2*)&As[buf][off] = make_uint2(ua[i][0], ua[i][1]);
            *(uint2*)&Bs[buf][off] = make_uint2(ub[i][0], ub[i][1]);
        }
    };

    // ldmatrix per-lane base addresses (bytes)
    int g = lane >> 3, r = lane & 7;
    uint32_t aBase[2], bBase[4];
    #pragma unroll
    for (int mt=0;mt<2;mt++)
        aBase[mt] = smem_u32p(&As[0][(wm + mt*16 + (g&1)*8 + r)*SROW + (g>>1)*4]);
    #pragma unroll
    for (int p=0;p<4;p++)
        bBase[p] = smem_u32p(&Bs[0][(wn + p*16 + (g>>1)*8 + r)*SROW + (g&1)*4]);

    float acc[2][8][4];
    #pragma unroll
    for (int mt=0;mt<2;mt++)
        #pragma unroll
        for (int nt=0;nt<8;nt++)
            #pragma unroll
            for (int q=0;q<4;q++) acc[mt][nt][q]=0.f;

    int nchunk = K / BKk;
    load_regs(0);
    store_smem(0);
    __syncthreads();

    for (int ck=0; ck<nchunk; ck++){
        int cur = ck & 1;
        if (ck+1 < nchunk) load_regs((ck+1)*BKk);

        uint32_t bufOff = cur * (BUFU32*4);
        #pragma unroll
        for (int ks=0; ks<2; ks++){
            uint32_t kOff = bufOff + ks*32;   // 16 bf16 = 32 bytes
            uint32_t af[2][4];
            #pragma unroll
            for (int mt=0;mt<2;mt++)
                ldsm4(af[mt][0], af[mt][1], af[mt][2], af[mt][3], aBase[mt] + kOff);
            uint32_t bf[8][2];
            #pragma unroll
            for (int p=0;p<4;p++)
                ldsm4(bf[2*p][0], bf[2*p][1], bf[2*p+1][0], bf[2*p+1][1], bBase[p] + kOff);
            #pragma unroll
            for (int mt=0;mt<2;mt++)
                #pragma unroll
                for (int nt=0;nt<8;nt++){
                    asm volatile(
                        "mma.sync.aligned.m16n8k16.row.col.f32.bf16.bf16.f32 "
                        "{%0,%1,%2,%3}, {%4,%5,%6,%7}, {%8,%9}, {%0,%1,%2,%3};\n"
                        : "+f"(acc[mt][nt][0]), "+f"(acc[mt][nt][1]),
                          "+f"(acc[mt][nt][2]), "+f"(acc[mt][nt][3])
                        : "r"(af[mt][0]), "r"(af[mt][1]), "r"(af[mt][2]), "r"(af[mt][3]),
                          "r"(bf[nt][0]), "r"(bf[nt][1]));
                }
        }

        if (ck+1 < nchunk){
            store_smem(cur ^ 1);
            __syncthreads();
        }
    }

    // Epilogue: acc[mt][nt]: rows (gid, gid+8), cols (tig*2, tig*2+1)
    #pragma unroll
    for (int mt=0;mt<2;mt++){
        int r0 = m0 + wm + mt*16 + gid;
        #pragma unroll
        for (int nt=0;nt<8;nt++){
            int c = n0 + wn + nt*8 + tig*2;
            if (c >= N) continue;
            float v[4];
            #pragma unroll
            for (int q=0;q<4;q++) v[q] = acc[mt][nt][q];
            if (EPI==1){
                #pragma unroll
                for (int q=0;q<4;q++){
                    float t = v[q] + bias[c + (q&1)];
                    v[q] = (t > 20.f) ? t : log1pf(expf(t));
                }
            }
            if (EPI==2){
                v[0] += bias[c]   + resid[(size_t)r0*ldc + c];
                v[1] += bias[c+1] + resid[(size_t)r0*ldc + c+1];
                v[2] += bias[c]   + resid[(size_t)(r0+8)*ldc + c];
                v[3] += bias[c+1] + resid[(size_t)(r0+8)*ldc + c+1];
            }
            *(float2*)(C + (size_t)r0*ldc + c)     = make_float2(v[0], v[1]);
            *(float2*)(C + (size_t)(r0+8)*ldc + c) = make_float2(v[2], v[3]);
        }
    }
}

// ---------------- Depthwise conv + bias + SiLU, both dirs --------------------
__global__ __launch_bounds__(256) void conv2_kernel(
    const float* __restrict__ xz_b, const float* __restrict__ cw0,
    const float* __restrict__ cw1, const float* __restrict__ cb0,
    const float* __restrict__ cb1, float* __restrict__ xc_b)
{
    int d = blockIdx.x*256 + threadIdx.x;
    int t = blockIdx.y;
    int z = blockIdx.z;
    int dir = z >> 2, b = z & 3;
    const float* xz = xz_b + (size_t)dir*NM*XZW;
    float* xc = xc_b + (size_t)dir*NM*DI;
    const float* cw = dir ? cw1 : cw0;
    const float* cb = dir ? cb1 : cb0;
    float w0 = cw[d*4+0], w1 = cw[d*4+1], w2 = cw[d*4+2], w3 = cw[d*4+3];
    float acc = cb[d];
    size_t rowb = (size_t)b*LL;
    if (!dir){
        if (t-3 >= 0) acc += w0 * xz[(rowb + t-3)*XZW + d];
        if (t-2 >= 0) acc += w1 * xz[(rowb + t-2)*XZW + d];
        if (t-1 >= 0) acc += w2 * xz[(rowb + t-1)*XZW + d];
        acc += w3 * xz[(rowb + t)*XZW + d];
    } else {
        acc += w3 * xz[(rowb + t)*XZW + d];
        if (t+1 < LL) acc += w2 * xz[(rowb + t+1)*XZW + d];
        if (t+2 < LL) acc += w1 * xz[(rowb + t+2)*XZW + d];
        if (t+3 < LL) acc += w0 * xz[(rowb + t+3)*XZW + d];
    }
    float s = acc / (1.f + expf(-acc));
    xc[((size_t)b*LL + t)*DI + d] = s;
}

// ---------------- FMA-only exp2 ----------------------------------------------
__device__ __forceinline__ float exp2p(float x){
    x = fmaxf(x, -126.f);
    float fl = floorf(x);
    float f = x - fl;
    float p = 1.5400277e-4f;
    p = fmaf(p, f, 1.3335581e-3f);
    p = fmaf(p, f, 9.6181290e-3f);
    p = fmaf(p, f, 5.5504110e-2f);
    p = fmaf(p, f, 2.4022651e-1f);
    p = fmaf(p, f, 6.9314718e-1f);
    p = fmaf(p, f, 1.0f);
    return p * __int_as_float(((int)fl + 127) << 23);
}

// ---------------- Selective scan (both dirs), prefetched ---------------------
// 2 threads per channel (8 states each); 256 thr = 128 channels/block.
__global__ __launch_bounds__(256) void scan2_kernel(
    const float* __restrict__ delta_b, const float* __restrict__ xc_b,
    const float* __restrict__ proj_b,  const float* __restrict__ xz_b,
    const float* __restrict__ A0, const float* __restrict__ A1,
    const float* __restrict__ D0, const float* __restrict__ D1,
    float* __restrict__ yg_b)
{
    __shared__ float sBC[2][32];
    int tid = threadIdx.x;
    int ch = tid >> 1, sg = tid & 1;
    int d = blockIdx.x*128 + ch;
    int b = blockIdx.y;
    int dir = blockIdx.z;
    const float* delta = delta_b + (size_t)dir*NM*DI;
    const float* xc    = xc_b    + (size_t)dir*NM*DI;
    const float* proj  = proj_b  + (size_t)dir*NM*PRW;
    const float* xz    = xz_b    + (size_t)dir*NM*XZW;
    const float* A_log = dir ? A1 : A0;
    float Dv = (dir ? D1 : D0)[d];
    float* yg = yg_b + (size_t)dir*NM*DI;
    const float L2E = 1.4426950408889634f;
    float c[8], h[8];
    #pragma unroll
    for (int i=0;i<8;i++){
        c[i] = -expf(A_log[(size_t)d*DS + sg*8 + i]) * L2E;
        h[i] = 0.f;
    }
    size_t rowb = (size_t)b*LL;
    int stp = dir ? -1 : 1;
    int t = dir ? LL-1 : 0;
    size_t m = rowb + t;
    float dlt = delta[m*DI + d];
    float xv  = xc[m*DI + d];
    float zv  = xz[m*XZW + DI + d];
    if (tid < 32) sBC[0][tid] = proj[m*PRW + DTR + tid];
    __syncthreads();

    for (int step = 0; step < LL; step++){
        int cb = step & 1;
        float dltn = 0.f, xvn = 0.f, zvn = 0.f;
        if (step+1 < LL){
            size_t mn = rowb + t + stp;
            dltn = delta[mn*DI + d];
            xvn  = xc[mn*DI + d];
            zvn  = xz[mn*XZW + DI + d];
            if (tid < 32) sBC[cb^1][tid] = proj[mn*PRW + DTR + tid];
        }
        float dx = dlt * xv;
        float y = 0.f;
        #pragma unroll
        for (int i=0;i<8;i++){
            float e = exp2p(dlt * c[i]);
            h[i] = fmaf(e, h[i], dx * sBC[cb][sg*8 + i]);
            y = fmaf(h[i], sBC[cb][16 + sg*8 + i], y);
        }
        y += __shfl_xor_sync(~0u, y, 1);
        if (sg == 0){
            float sz = zv / (1.f + expf(-zv));
            yg[(rowb + t)*DI + d] = (y + xv*Dv) * sz;
        }
        dlt = dltn; xv = xvn; zv = zvn;
        t += stp;
        __syncthreads();
    }
}

// ---------------- Host launcher ---------------------------------------------
extern "C" void kernel_launch(void* const* d_in, const int* in_sizes, int n_in,
                              void* d_out, int out_size)
{
    const float* X       = (const float*)d_in[0];
    const float* ln_g    = (const float*)d_in[1];
    const float* ln_b    = (const float*)d_in[2];
    const float* merge_w = (const float*)d_in[3];
    const float* merge_b = (const float*)d_in[4];

    float *xn_p, *xz_p, *xc_p, *proj_p, *delta_p, *yg_p, *ycat_p;
    cudaGetSymbolAddress((void**)&xn_p,   g_xn);
    cudaGetSymbolAddress((void**)&xz_p,   g_xz);
    cudaGetSymbolAddress((void**)&xc_p,   g_xc);
    cudaGetSymbolAddress((void**)&proj_p, g_proj);
    cudaGetSymbolAddress((void**)&delta_p,g_delta);
    cudaGetSymbolAddress((void**)&yg_p,   g_yg);
    cudaGetSymbolAddress((void**)&ycat_p, g_ycat);

    const float* W[2][9];
    for (int dir = 0; dir < 2; dir++)
        for (int i = 0; i < 9; i++)
            W[dir][i] = (const float*)d_in[5 + dir*9 + i];
    // index: 0 in_w, 1 conv_w, 2 conv_b, 3 xproj_w, 4 dt_w, 5 dt_b, 6 A_log, 7 D, 8 out_w

    // 1. LayerNorm
    ln_kernel<<<NM, 256>>>(X, ln_g, ln_b, xn_p);

    // 2. in-proj both dirs: xz = xn @ in_w.T   [8192,4096] K=1024
    for (int dir = 0; dir < 2; dir++)
        gemm_bf16<0><<<dim3(XZW/128, NM/128), 256>>>(
            xn_p, W[dir][0], xz_p + (size_t)dir*NM*XZW,
            NM, XZW, DM, DM, DM, XZW, nullptr, nullptr);

    // 3. depthwise conv + SiLU, both dirs fused
    conv2_kernel<<<dim3(DI/256, LL, 2*BB), 256>>>(
        xz_p, W[0][1], W[1][1], W[0][2], W[1][2], xc_p);

    // 4. x-proj both dirs: [8192,96] K=2048
    for (int dir = 0; dir < 2; dir++)
        gemm_bf16<0><<<dim3(1, NM/128), 256>>>(
            xc_p + (size_t)dir*NM*DI, W[dir][3], proj_p + (size_t)dir*NM*PRW,
            NM, PRW, DI, DI, DI, PRW, nullptr, nullptr);

    // 5. delta both dirs: softplus(dt @ dt_w.T + dt_b)  [8192,2048] K=64
    for (int dir = 0; dir < 2; dir++)
        gemm_bf16<1><<<dim3(DI/128, NM/128), 256>>>(
            proj_p + (size_t)dir*NM*PRW, W[dir][4], delta_p + (size_t)dir*NM*DI,
            NM, DI, DTR, PRW, DTR, DI, W[dir][5], nullptr);

    // 6. selective scan + gate, both dirs in one launch
    scan2_kernel<<<dim3(DI/128, BB, 2), 256>>>(
        delta_p, xc_p, proj_p, xz_p,
        W[0][6], W[1][6], W[0][7], W[1][7], yg_p);

    // 7. out-proj both dirs into concat buffer: [8192,1024] K=2048
    for (int dir = 0; dir < 2; dir++)
        gemm_bf16<0><<<dim3(DM/128, NM/128), 256>>>(
            yg_p + (size_t)dir*NM*DI, W[dir][8], ycat_p + (size_t)dir*DM,
            NM, DM, DI, DI, DI, DI, nullptr, nullptr);

    // 8. merge + bias + residual: out = x + ycat @ merge_w.T + merge_b
    gemm_bf16<2><<<dim3(DM/128, NM/128), 256>>>(
        ycat_p, merge_w, (float*)d_out, NM, DM, DI, DI, DI, DM, merge_b, X);
}

// round 6
// speedup vs baseline: 6.5591x; 1.3321x over previous
#include <cuda_runtime.h>
#include <cuda_bf16.h>
#include <cstdint>

// Problem constants
#define BB   4
#define LL   2048
#define DM   1024
#define DI   2048
#define NM   (BB*LL)      // 8192 tokens
#define XZW  4096         // 2*DI
#define PRW  96           // dt_rank + 2*d_state
#define DTR  64
#define DS   16

typedef __nv_bfloat16 bf16;
typedef __nv_bfloat162 bf162;

// ---------------- scratch (device globals; allocation-free rule) -------------
__device__ bf16  g_xn[(size_t)NM*DM];
__device__ bf16  g_xz[2][(size_t)NM*XZW];
__device__ bf16  g_xc[2][(size_t)NM*DI];
__device__ float g_xpart[2][4][(size_t)NM*PRW];
__device__ bf16  g_projbf[2][(size_t)NM*PRW];
__device__ float g_delta[2][(size_t)NM*DI];
__device__ bf16  g_yg[2][(size_t)NM*DI];
__device__ bf16  g_ycat[(size_t)NM*DI];
__device__ bf16  g_wbf[15335424];   // all weights converted to bf16

__device__ __forceinline__ uint32_t pack_bf2(float x, float y){
    bf162 h = __float22bfloat162_rn(make_float2(x, y));
    return *(uint32_t*)&h;
}
__device__ __forceinline__ float2 unpack_bf2(uint32_t u){
    bf162 h = *(bf162*)&u;
    return __bfloat1622float2(h);
}

// ---------------- weight fp32 -> bf16 ---------------------------------------
__global__ __launch_bounds__(256) void cvt_bf_kernel(
    const float* __restrict__ in, bf16* __restrict__ out, int n4)
{
    int i = blockIdx.x*256 + threadIdx.x;
    if (i < n4){
        float4 v = ((const float4*)in)[i];
        uint2 o = make_uint2(pack_bf2(v.x, v.y), pack_bf2(v.z, v.w));
        ((uint2*)out)[i] = o;
    }
}

// ---------------- LayerNorm (fp32 in, bf16 out) ------------------------------
__global__ __launch_bounds__(256) void ln_kernel(
    const float* __restrict__ x, const float* __restrict__ gw,
    const float* __restrict__ bw, bf16* __restrict__ xn)
{
    __shared__ float red[16];
    int m = blockIdx.x, tid = threadIdx.x;
    const float4* xr = (const float4*)(x + (size_t)m*DM);
    float4 v = xr[tid];
    float s  = v.x+v.y+v.z+v.w;
    float ss = v.x*v.x+v.y*v.y+v.z*v.z+v.w*v.w;
    #pragma unroll
    for (int o=16;o;o>>=1){ s += __shfl_xor_sync(~0u,s,o); ss += __shfl_xor_sync(~0u,ss,o); }
    if ((tid&31)==0){ red[tid>>5]=s; red[8+(tid>>5)]=ss; }
    __syncthreads();
    if (tid<32){
        float a  = (tid<8)? red[tid]   : 0.f;
        float b2 = (tid<8)? red[8+tid] : 0.f;
        #pragma unroll
        for (int o=4;o;o>>=1){ a += __shfl_xor_sync(~0u,a,o); b2 += __shfl_xor_sync(~0u,b2,o); }
        if (tid==0){ red[0]=a; red[8]=b2; }
    }
    __syncthreads();
    float mu   = red[0]*(1.0f/DM);
    float var  = red[8]*(1.0f/DM) - mu*mu;
    float rstd = rsqrtf(var + 1e-5f);
    float4 g4 = ((const float4*)gw)[tid];
    float4 b4 = ((const float4*)bw)[tid];
    uint2 o = make_uint2(
        pack_bf2((v.x-mu)*rstd*g4.x + b4.x, (v.y-mu)*rstd*g4.y + b4.y),
        pack_bf2((v.z-mu)*rstd*g4.z + b4.z, (v.w-mu)*rstd*g4.w + b4.w));
    ((uint2*)(xn + (size_t)m*DM))[tid] = o;
}

// ---------------- BF16 tensor-core GEMM, NT ----------------------------------
// A bf16 [M,K] lda, B bf16 [N,K] ldb, C = TOUT. 128x128x32 tile, 8 warps,
// m16n8k16 bf16 mma, double-buffered smem, ldmatrix loads.
// blockIdx.z = K-slice (A,B advance z*K; C advances z*csplit).
// EPI: 0 none, 1 softplus(acc+bias), 2 acc+bias+resid.
#define BKk 32
#define SROW 20          // row stride in u32: 16 (32 bf16) + 4 pad
#define BUFU32 (128*SROW)

__device__ __forceinline__ uint32_t smem_u32p(const void* p){
    return (uint32_t)__cvta_generic_to_shared(p);
}
__device__ __forceinline__ void ldsm4(uint32_t& r0, uint32_t& r1, uint32_t& r2, uint32_t& r3, uint32_t a){
    asm volatile("ldmatrix.sync.aligned.m8n8.x4.shared.b16 {%0,%1,%2,%3}, [%4];\n"
        : "=r"(r0), "=r"(r1), "=r"(r2), "=r"(r3) : "r"(a));
}

template<int EPI, typename TOUT>
__global__ __launch_bounds__(256) void gemm_bf16(
    const bf16* __restrict__ A, const bf16* __restrict__ B, TOUT* __restrict__ C,
    int M, int N, int K, int lda, int ldb, int ldc, size_t csplit,
    const float* __restrict__ bias, const float* __restrict__ resid)
{
    __shared__ uint32_t As[2][BUFU32];
    __shared__ uint32_t Bs[2][BUFU32];

    A += (size_t)blockIdx.z * K;
    B += (size_t)blockIdx.z * K;
    C += (size_t)blockIdx.z * csplit;

    int tid  = threadIdx.x;
    int warp = tid >> 5, lane = tid & 31;
    int gid  = lane >> 2, tig = lane & 3;
    int wm   = (warp >> 1) * 32;
    int wn   = (warp & 1) * 64;
    int m0 = blockIdx.y * 128, n0 = blockIdx.x * 128;

    // staging: slot s (0..511): row = s>>2, kq = (s&3)*8 (bf16 elems)
    int srow[2], skq[2];
    #pragma unroll
    for (int i=0;i<2;i++){ int s = tid + i*256; srow[i] = s>>2; skq[i] = (s&3)*8; }

    uint4 ga[2], gb[2];
    auto load_regs = [&](int k0){
        #pragma unroll
        for (int i=0;i<2;i++){
            ga[i] = *(const uint4*)(A + (size_t)(m0+srow[i])*lda + k0 + skq[i]);
            int nrow = n0 + srow[i];
            gb[i] = (nrow < N) ? *(const uint4*)(B + (size_t)nrow*ldb + k0 + skq[i])
                               : make_uint4(0,0,0,0);
        }
    };
    auto store_smem = [&](int buf){
        #pragma unroll
        for (int i=0;i<2;i++){
            int off = srow[i]*SROW + (skq[i]>>1);
            *(uint4*)&As[buf][off] = ga[i];
            *(uint4*)&Bs[buf][off] = gb[i];
        }
    };

    int g = lane >> 3, r = lane & 7;
    uint32_t aBase[2], bBase[4];
    #pragma unroll
    for (int mt=0;mt<2;mt++)
        aBase[mt] = smem_u32p(&As[0][(wm + mt*16 + (g&1)*8 + r)*SROW + (g>>1)*4]);
    #pragma unroll
    for (int p=0;p<4;p++)
        bBase[p] = smem_u32p(&Bs[0][(wn + p*16 + (g>>1)*8 + r)*SROW + (g&1)*4]);

    float acc[2][8][4];
    #pragma unroll
    for (int mt=0;mt<2;mt++)
        #pragma unroll
        for (int nt=0;nt<8;nt++)
            #pragma unroll
            for (int q=0;q<4;q++) acc[mt][nt][q]=0.f;

    int nchunk = K / BKk;
    load_regs(0);
    store_smem(0);
    __syncthreads();

    for (int ck=0; ck<nchunk; ck++){
        int cur = ck & 1;
        if (ck+1 < nchunk) load_regs((ck+1)*BKk);

        uint32_t bufOff = cur * (BUFU32*4);
        #pragma unroll
        for (int ks=0; ks<2; ks++){
            uint32_t kOff = bufOff + ks*32;
            uint32_t af[2][4];
            #pragma unroll
            for (int mt=0;mt<2;mt++)
                ldsm4(af[mt][0], af[mt][1], af[mt][2], af[mt][3], aBase[mt] + kOff);
            uint32_t bf[8][2];
            #pragma unroll
            for (int p=0;p<4;p++)
                ldsm4(bf[2*p][0], bf[2*p][1], bf[2*p+1][0], bf[2*p+1][1], bBase[p] + kOff);
            #pragma unroll
            for (int mt=0;mt<2;mt++)
                #pragma unroll
                for (int nt=0;nt<8;nt++){
                    asm volatile(
                        "mma.sync.aligned.m16n8k16.row.col.f32.bf16.bf16.f32 "
                        "{%0,%1,%2,%3}, {%4,%5,%6,%7}, {%8,%9}, {%0,%1,%2,%3};\n"
                        : "+f"(acc[mt][nt][0]), "+f"(acc[mt][nt][1]),
                          "+f"(acc[mt][nt][2]), "+f"(acc[mt][nt][3])
                        : "r"(af[mt][0]), "r"(af[mt][1]), "r"(af[mt][2]), "r"(af[mt][3]),
                          "r"(bf[nt][0]), "r"(bf[nt][1]));
                }
        }

        if (ck+1 < nchunk){
            store_smem(cur ^ 1);
            __syncthreads();
        }
    }

    // Epilogue
    #pragma unroll
    for (int mt=0;mt<2;mt++){
        int r0 = m0 + wm + mt*16 + gid;
        #pragma unroll
        for (int nt=0;nt<8;nt++){
            int c = n0 + wn + nt*8 + tig*2;
            if (c >= N) continue;
            float v[4];
            #pragma unroll
            for (int q=0;q<4;q++) v[q] = acc[mt][nt][q];
            if (EPI==1){
                #pragma unroll
                for (int q=0;q<4;q++){
                    float t = v[q] + bias[c + (q&1)];
                    v[q] = (t > 20.f) ? t : log1pf(expf(t));
                }
            }
            if (EPI==2){
                v[0] += bias[c]   + resid[(size_t)r0*ldc + c];
                v[1] += bias[c+1] + resid[(size_t)r0*ldc + c+1];
                v[2] += bias[c]   + resid[(size_t)(r0+8)*ldc + c];
                v[3] += bias[c+1] + resid[(size_t)(r0+8)*ldc + c+1];
            }
            if (sizeof(TOUT) == 4){
                *(float2*)((float*)C + (size_t)r0*ldc + c)     = make_float2(v[0], v[1]);
                *(float2*)((float*)C + (size_t)(r0+8)*ldc + c) = make_float2(v[2], v[3]);
            } else {
                *(uint32_t*)((bf16*)C + (size_t)r0*ldc + c)     = pack_bf2(v[0], v[1]);
                *(uint32_t*)((bf16*)C + (size_t)(r0+8)*ldc + c) = pack_bf2(v[2], v[3]);
            }
        }
    }
}

// ---------------- split-K reduce: 4 fp32 slabs -> bf16 -----------------------
__global__ __launch_bounds__(256) void reduce4_kernel(
    const float* __restrict__ part, bf16* __restrict__ out, int n)
{
    int i = blockIdx.x*256 + threadIdx.x;
    if (i < n){
        float s = part[i] + part[i+n] + part[i+2*n] + part[i+3*n];
        out[i] = __float2bfloat16(s);
    }
}

// ---------------- Depthwise conv + bias + SiLU, time-tiled, both dirs --------
// Thread: one bf16x2 channel pair, 8 timesteps. Block 256 thr.
__global__ __launch_bounds__(256) void conv2_kernel(
    const bf16* __restrict__ xz_b, const float* __restrict__ cw0,
    const float* __restrict__ cw1, const float* __restrict__ cb0,
    const float* __restrict__ cb1, bf16* __restrict__ xc_b)
{
    int dp = blockIdx.x*256 + threadIdx.x;   // 0..1023 channel pairs
    int d0 = dp*2;
    int t0 = blockIdx.y*8;
    int z = blockIdx.z;
    int dir = z >> 2, b = z & 3;
    const bf16* xz = xz_b + (size_t)dir*NM*XZW;
    bf16* xc = xc_b + (size_t)dir*NM*DI;
    const float* cw = dir ? cw1 : cw0;
    const float* cb = dir ? cb1 : cb0;
    float4 wa = *(const float4*)(cw + d0*4);
    float4 wb = *(const float4*)(cw + d0*4 + 4);
    float cba = cb[d0], cbb = cb[d0+1];
    size_t rowb = (size_t)b*LL;

    float2 vals[11];
    #pragma unroll
    for (int j=0;j<11;j++){
        int t = dir ? (t0 + j) : (t0 - 3 + j);
        if (t >= 0 && t < LL){
            uint32_t u = *(const uint32_t*)(xz + (rowb + t)*XZW + d0);
            vals[j] = unpack_bf2(u);
        } else vals[j] = make_float2(0.f, 0.f);
    }
    #pragma unroll
    for (int i=0;i<8;i++){
        float ax, ay;
        if (!dir){
            ax = cba + wa.x*vals[i].x + wa.y*vals[i+1].x + wa.z*vals[i+2].x + wa.w*vals[i+3].x;
            ay = cbb + wb.x*vals[i].y + wb.y*vals[i+1].y + wb.z*vals[i+2].y + wb.w*vals[i+3].y;
        } else {
            ax = cba + wa.w*vals[i].x + wa.z*vals[i+1].x + wa.y*vals[i+2].x + wa.x*vals[i+3].x;
            ay = cbb + wb.w*vals[i].y + wb.z*vals[i+1].y + wb.y*vals[i+2].y + wb.x*vals[i+3].y;
        }
        float sx = ax / (1.f + expf(-ax));
        float sy = ay / (1.f + expf(-ay));
        *(uint32_t*)(xc + (rowb + t0 + i)*DI + d0) = pack_bf2(sx, sy);
    }
}

// ---------------- FMA-only exp2 ----------------------------------------------
__device__ __forceinline__ float exp2p(float x){
    x = fmaxf(x, -126.f);
    float fl = floorf(x);
    float f = x - fl;
    float p = 1.5400277e-4f;
    p = fmaf(p, f, 1.3335581e-3f);
    p = fmaf(p, f, 9.6181290e-3f);
    p = fmaf(p, f, 5.5504110e-2f);
    p = fmaf(p, f, 2.4022651e-1f);
    p = fmaf(p, f, 6.9314718e-1f);
    p = fmaf(p, f, 1.0f);
    return p * __int_as_float(((int)fl + 127) << 23);
}

// ---------------- Selective scan: warp-autonomous, no barriers ---------------
// 2 thr/channel (8 states each), 16 channels/warp, BC via shfl, reg prefetch.
__global__ __launch_bounds__(256) void scan2_kernel(
    const float* __restrict__ delta_b, const bf16* __restrict__ xc_b,
    const bf16* __restrict__ proj_b,  const bf16* __restrict__ xz_b,
    const float* __restrict__ A0, const float* __restrict__ A1,
    const float* __restrict__ D0, const float* __restrict__ D1,
    bf16* __restrict__ yg_b)
{
    int tid = threadIdx.x;
    int warp = tid >> 5, lane = tid & 31;
    int ch = lane >> 1, sg = lane & 1;
    int d = blockIdx.x*128 + warp*16 + ch;
    int b = blockIdx.y;
    int dir = blockIdx.z;
    const float* delta = delta_b + (size_t)dir*NM*DI;
    const bf16* xc    = xc_b    + (size_t)dir*NM*DI;
    const bf16* proj  = proj_b  + (size_t)dir*NM*PRW;
    const bf16* xz    = xz_b    + (size_t)dir*NM*XZW;
    const float* A_log = dir ? A1 : A0;
    float Dv = (dir ? D1 : D0)[d];
    bf16* yg = yg_b + (size_t)dir*NM*DI;
    const float L2E = 1.4426950408889634f;
    float c[8], h[8];
    #pragma unroll
    for (int i=0;i<8;i++){
        c[i] = -expf(A_log[(size_t)d*DS + sg*8 + i]) * L2E;
        h[i] = 0.f;
    }
    size_t rowb = (size_t)b*LL;
    int stp = dir ? -1 : 1;
    int t = dir ? LL-1 : 0;
    size_t m = rowb + t;
    float dlt = delta[m*DI + d];
    float xv  = __bfloat162float(xc[m*DI + d]);
    float zv  = __bfloat162float(xz[m*XZW + DI + d]);
    float bc  = __bfloat162float(proj[m*PRW + DTR + lane]);

    for (int step = 0; step < LL; step++){
        float dltn = 0.f, xvn = 0.f, zvn = 0.f, bcn = 0.f;
        if (step+1 < LL){
            size_t mn = m + stp;
            dltn = delta[mn*DI + d];
            xvn  = __bfloat162float(xc[mn*DI + d]);
            zvn  = __bfloat162float(xz[mn*XZW + DI + d]);
            bcn  = __bfloat162float(proj[mn*PRW + DTR + lane]);
        }
        float dx = dlt * xv;
        float y = 0.f;
        #pragma unroll
        for (int i=0;i<8;i++){
            float Bv = __shfl_sync(~0u, bc, sg*8 + i);
            float Cv = __shfl_sync(~0u, bc, 16 + sg*8 + i);
            float e = exp2p(dlt * c[i]);
            h[i] = fmaf(e, h[i], dx * Bv);
            y = fmaf(h[i], Cv, y);
        }
        y += __shfl_xor_sync(~0u, y, 1);
        if (sg == 0){
            float sz = zv / (1.f + expf(-zv));
            yg[m*DI + d] = __float2bfloat16((y + xv*Dv) * sz);
        }
        dlt = dltn; xv = xvn; zv = zvn; bc = bcn;
        m += stp;
    }
}

// ---------------- Host launcher ---------------------------------------------
extern "C" void kernel_launch(void* const* d_in, const int* in_sizes, int n_in,
                              void* d_out, int out_size)
{
    const float* X       = (const float*)d_in[0];
    const float* ln_g    = (const float*)d_in[1];
    const float* ln_b    = (const float*)d_in[2];
    const float* merge_w = (const float*)d_in[3];
    const float* merge_b = (const float*)d_in[4];

    bf16 *xn_p, *xz_p, *xc_p, *projbf_p, *yg_p, *ycat_p, *wbf_p;
    float *xpart_p, *delta_p;
    cudaGetSymbolAddress((void**)&xn_p,    g_xn);
    cudaGetSymbolAddress((void**)&xz_p,    g_xz);
    cudaGetSymbolAddress((void**)&xc_p,    g_xc);
    cudaGetSymbolAddress((void**)&xpart_p, g_xpart);
    cudaGetSymbolAddress((void**)&projbf_p,g_projbf);
    cudaGetSymbolAddress((void**)&delta_p, g_delta);
    cudaGetSymbolAddress((void**)&yg_p,    g_yg);
    cudaGetSymbolAddress((void**)&ycat_p,  g_ycat);
    cudaGetSymbolAddress((void**)&wbf_p,   g_wbf);

    const float* W[2][9];
    for (int dir = 0; dir < 2; dir++)
        for (int i = 0; i < 9; i++)
            W[dir][i] = (const float*)d_in[5 + dir*9 + i];
    // 0 in_w, 1 conv_w, 2 conv_b, 3 xproj_w, 4 dt_w, 5 dt_b, 6 A_log, 7 D, 8 out_w

    // bf16 weight offsets
    const size_t o_in[2]   = {0, 4194304};
    const size_t o_xp[2]   = {8388608, 8585216};
    const size_t o_dtw[2]  = {8781824, 8912896};
    const size_t o_out[2]  = {9043968, 11141120};
    const size_t o_mg      = 13238272;

    // 0. convert weights to bf16
    for (int dir = 0; dir < 2; dir++){
        cvt_bf_kernel<<<(4194304/4+255)/256,256>>>(W[dir][0], wbf_p + o_in[dir],  4194304/4);
        cvt_bf_kernel<<<(196608/4+255)/256, 256>>>(W[dir][3], wbf_p + o_xp[dir],  196608/4);
        cvt_bf_kernel<<<(131072/4+255)/256, 256>>>(W[dir][4], wbf_p + o_dtw[dir], 131072/4);
        cvt_bf_kernel<<<(2097152/4+255)/256,256>>>(W[dir][8], wbf_p + o_out[dir], 2097152/4);
    }
    cvt_bf_kernel<<<(2097152/4+255)/256,256>>>(merge_w, wbf_p + o_mg, 2097152/4);

    // 1. LayerNorm -> bf16
    ln_kernel<<<NM, 256>>>(X, ln_g, ln_b, xn_p);

    // 2. in-proj both dirs: [8192,4096] K=1024 -> bf16
    for (int dir = 0; dir < 2; dir++)
        gemm_bf16<0,bf16><<<dim3(XZW/128, NM/128, 1), 256>>>(
            xn_p, wbf_p + o_in[dir], xz_p + (size_t)dir*NM*XZW,
            NM, XZW, DM, DM, DM, XZW, 0, nullptr, nullptr);

    // 3. depthwise conv + SiLU, both dirs, time-tiled
    conv2_kernel<<<dim3(4, LL/8, 2*BB), 256>>>(
        xz_p, W[0][1], W[1][1], W[0][2], W[1][2], xc_p);

    // 4. x-proj both dirs: [8192,96] K=2048, split-K=4 -> fp32 partials
    for (int dir = 0; dir < 2; dir++)
        gemm_bf16<0,float><<<dim3(1, NM/128, 4), 256>>>(
            xc_p + (size_t)dir*NM*DI, wbf_p + o_xp[dir],
            xpart_p + (size_t)dir*4*NM*PRW,
            NM, PRW, 512, DI, DI, PRW, (size_t)NM*PRW, nullptr, nullptr);

    // 4b. reduce partials -> bf16 proj
    for (int dir = 0; dir < 2; dir++)
        reduce4_kernel<<<(NM*PRW+255)/256, 256>>>(
            xpart_p + (size_t)dir*4*NM*PRW, projbf_p + (size_t)dir*NM*PRW, NM*PRW);

    // 5. delta both dirs: softplus(dt @ dt_w.T + dt_b)  [8192,2048] K=64
    for (int dir = 0; dir < 2; dir++)
        gemm_bf16<1,float><<<dim3(DI/128, NM/128, 1), 256>>>(
            projbf_p + (size_t)dir*NM*PRW, wbf_p + o_dtw[dir], delta_p + (size_t)dir*NM*DI,
            NM, DI, DTR, PRW, DTR, DI, 0, W[dir][5], nullptr);

    // 6. selective scan + gate, both dirs
    scan2_kernel<<<dim3(DI/128, BB, 2), 256>>>(
        delta_p, xc_p, projbf_p, xz_p,
        W[0][6], W[1][6], W[0][7], W[1][7], yg_p);

    // 7. out-proj both dirs into concat buffer: [8192,1024] K=2048 -> bf16
    for (int dir = 0; dir < 2; dir++)
        gemm_bf16<0,bf16><<<dim3(DM/128, NM/128, 1), 256>>>(
            yg_p + (size_t)dir*NM*DI, wbf_p + o_out[dir], ycat_p + (size_t)dir*DM,
            NM, DM, DI, DI, DI, DI, 0, nullptr, nullptr);

    // 8. merge + bias + residual -> fp32 out
    gemm_bf16<2,float><<<dim3(DM/128, NM/128, 1), 256>>>(
        ycat_p, wbf_p + o_mg, (float*)d_out, NM, DM, DI, DI, DI, DM, 0, merge_b, X);
}

// round 7
// speedup vs baseline: 7.0520x; 1.0752x over previous
#include <cuda_runtime.h>
#include <cuda_bf16.h>
#include <cstdint>

// Problem constants
#define BB   4
#define LL   2048
#define DM   1024
#define DI   2048
#define NM   (BB*LL)      // 8192 tokens
#define XZW  4096         // 2*DI
#define PRW  96           // dt_rank + 2*d_state
#define DTR  64
#define DS   16

typedef __nv_bfloat16 bf16;
typedef __nv_bfloat162 bf162;

// ---------------- scratch (device globals; allocation-free rule) -------------
__device__ bf16  g_xn[(size_t)NM*DM];
__device__ bf16  g_xz[2][(size_t)NM*XZW];
__device__ bf16  g_xc[2][(size_t)NM*DI];
__device__ float g_xpart[2][4][(size_t)NM*PRW];
__device__ bf16  g_projbf[2][(size_t)NM*PRW];
__device__ float g_delta[2][(size_t)NM*DI];
__device__ bf16  g_yg[2][(size_t)NM*DI];
__device__ bf16  g_ycat[(size_t)NM*DI];
__device__ bf16  g_wbf[15335424];   // all weights converted to bf16

__device__ __forceinline__ uint32_t pack_bf2(float x, float y){
    bf162 h = __float22bfloat162_rn(make_float2(x, y));
    return *(uint32_t*)&h;
}
__device__ __forceinline__ float2 unpack_bf2(uint32_t u){
    bf162 h = *(bf162*)&u;
    return __bfloat1622float2(h);
}

// ---------------- fused weight fp32 -> bf16 (all 9 weights, one launch) ------
__global__ __launch_bounds__(256) void cvt_all_kernel(
    const float* __restrict__ p0, const float* __restrict__ p1,
    const float* __restrict__ p2, const float* __restrict__ p3,
    const float* __restrict__ p4, const float* __restrict__ p5,
    const float* __restrict__ p6, const float* __restrict__ p7,
    const float* __restrict__ p8, bf16* __restrict__ out)
{
    size_t i = (size_t)blockIdx.x*256 + threadIdx.x;   // quad (float4) index
    if (i >= 3833856) return;
    const size_t cum[10] = {0,1048576,2097152,2146304,2195456,2228224,
                            2260992,2785280,3309568,3833856};
    const float* ps[9] = {p0,p1,p2,p3,p4,p5,p6,p7,p8};
    int seg = 0;
    #pragma unroll
    for (int s=0; s<9; s++) if (i >= cum[s+1]) seg = s+1;
    const float4* src = (const float4*)ps[seg];
    float4 v = src[i - cum[seg]];
    ((uint2*)out)[i] = make_uint2(pack_bf2(v.x, v.y), pack_bf2(v.z, v.w));
}

// ---------------- LayerNorm (fp32 in, bf16 out) ------------------------------
__global__ __launch_bounds__(256) void ln_kernel(
    const float* __restrict__ x, const float* __restrict__ gw,
    const float* __restrict__ bw, bf16* __restrict__ xn)
{
    __shared__ float red[16];
    int m = blockIdx.x, tid = threadIdx.x;
    const float4* xr = (const float4*)(x + (size_t)m*DM);
    float4 v = xr[tid];
    float s  = v.x+v.y+v.z+v.w;
    float ss = v.x*v.x+v.y*v.y+v.z*v.z+v.w*v.w;
    #pragma unroll
    for (int o=16;o;o>>=1){ s += __shfl_xor_sync(~0u,s,o); ss += __shfl_xor_sync(~0u,ss,o); }
    if ((tid&31)==0){ red[tid>>5]=s; red[8+(tid>>5)]=ss; }
    __syncthreads();
    if (tid<32){
        float a  = (tid<8)? red[tid]   : 0.f;
        float b2 = (tid<8)? red[8+tid] : 0.f;
        #pragma unroll
        for (int o=4;o;o>>=1){ a += __shfl_xor_sync(~0u,a,o); b2 += __shfl_xor_sync(~0u,b2,o); }
        if (tid==0){ red[0]=a; red[8]=b2; }
    }
    __syncthreads();
    float mu   = red[0]*(1.0f/DM);
    float var  = red[8]*(1.0f/DM) - mu*mu;
    float rstd = rsqrtf(var + 1e-5f);
    float4 g4 = ((const float4*)gw)[tid];
    float4 b4 = ((const float4*)bw)[tid];
    uint2 o = make_uint2(
        pack_bf2((v.x-mu)*rstd*g4.x + b4.x, (v.y-mu)*rstd*g4.y + b4.y),
        pack_bf2((v.z-mu)*rstd*g4.z + b4.z, (v.w-mu)*rstd*g4.w + b4.w));
    ((uint2*)(xn + (size_t)m*DM))[tid] = o;
}

// ---------------- BF16 tensor-core GEMM, NT ----------------------------------
// 128x128x32 tile, 8 warps, m16n8k16 bf16 mma, 3-stage cp.async pipeline,
// ldmatrix fragment loads, dynamic smem (60KB), 2 CTAs/SM.
// blockIdx.z = K-slice (A,B advance z*K; C advances z*csplit).
// EPI: 0 none, 1 softplus(acc+bias), 2 acc+bias+resid.
#define BKk 32
#define SROW 20          // row stride in u32: 16 (32 bf16) + 4 pad
#define BUFU32 (128*SROW)
#define GSMEM (6*BUFU32*4)   // 3 stages x (A+B) x 10240B = 61440

__device__ __forceinline__ uint32_t smem_u32p(const void* p){
    return (uint32_t)__cvta_generic_to_shared(p);
}
__device__ __forceinline__ void ldsm4(uint32_t& r0, uint32_t& r1, uint32_t& r2, uint32_t& r3, uint32_t a){
    asm volatile("ldmatrix.sync.aligned.m8n8.x4.shared.b16 {%0,%1,%2,%3}, [%4];\n"
        : "=r"(r0), "=r"(r1), "=r"(r2), "=r"(r3) : "r"(a));
}
__device__ __forceinline__ void cp_async16(uint32_t dst, const void* src, int srcsize){
    asm volatile("cp.async.cg.shared.global [%0], [%1], 16, %2;\n"
        :: "r"(dst), "l"(src), "r"(srcsize));
}

template<int EPI, typename TOUT>
__global__ __launch_bounds__(256, 2) void gemm_bf16(
    const bf16* __restrict__ A, const bf16* __restrict__ B, TOUT* __restrict__ C,
    int M, int N, int K, int lda, int ldb, int ldc, size_t csplit,
    const float* __restrict__ bias, const float* __restrict__ resid)
{
    extern __shared__ uint32_t sm[];
    uint32_t* As = sm;               // 3*BUFU32
    uint32_t* Bs = sm + 3*BUFU32;    // 3*BUFU32

    A += (size_t)blockIdx.z * K;
    B += (size_t)blockIdx.z * K;
    C += (size_t)blockIdx.z * csplit;

    int tid  = threadIdx.x;
    int warp = tid >> 5, lane = tid & 31;
    int gid  = lane >> 2, tig = lane & 3;
    int wm   = (warp >> 1) * 32;
    int wn   = (warp & 1) * 64;
    int m0 = blockIdx.y * 128, n0 = blockIdx.x * 128;

    // staging: slot s (0..511): row = s>>2, seg = s&3 (16B segment)
    int srow[2], sseg[2];
    #pragma unroll
    for (int i=0;i<2;i++){ int s = tid + i*256; srow[i] = s>>2; sseg[i] = s&3; }

    auto issue = [&](int buf, int k0){
        uint32_t* Ab = As + buf*BUFU32;
        uint32_t* Bb = Bs + buf*BUFU32;
        #pragma unroll
        for (int i=0;i<2;i++){
            const bf16* sa = A + (size_t)(m0+srow[i])*lda + k0 + sseg[i]*8;
            cp_async16(smem_u32p(Ab + srow[i]*SROW + sseg[i]*4), sa, 16);
            int nrow = n0 + srow[i];
            const bf16* sb = B + (size_t)nrow*ldb + k0 + sseg[i]*8;
            cp_async16(smem_u32p(Bb + srow[i]*SROW + sseg[i]*4), sb, (nrow<N)?16:0);
        }
        asm volatile("cp.async.commit_group;\n" ::: "memory");
    };

    int g = lane >> 3, r = lane & 7;
    uint32_t aBase[2], bBase[4];
    #pragma unroll
    for (int mt=0;mt<2;mt++)
        aBase[mt] = smem_u32p(&As[(wm + mt*16 + (g&1)*8 + r)*SROW + (g>>1)*4]);
    #pragma unroll
    for (int p=0;p<4;p++)
        bBase[p] = smem_u32p(&Bs[(wn + p*16 + (g>>1)*8 + r)*SROW + (g&1)*4]);

    float acc[2][8][4];
    #pragma unroll
    for (int mt=0;mt<2;mt++)
        #pragma unroll
        for (int nt=0;nt<8;nt++)
            #pragma unroll
            for (int q=0;q<4;q++) acc[mt][nt][q]=0.f;

    int nchunk = K / BKk;
    issue(0, 0);
    if (nchunk > 1) issue(1, BKk);

    for (int ck=0; ck<nchunk; ck++){
        if (ck+1 < nchunk) asm volatile("cp.async.wait_group 1;\n" ::: "memory");
        else               asm volatile("cp.async.wait_group 0;\n" ::: "memory");
        __syncthreads();
        if (ck+2 < nchunk) issue((ck+2)%3, (ck+2)*BKk);

        uint32_t bufOff = (uint32_t)(ck%3) * (BUFU32*4);
        #pragma unroll
        for (int ks=0; ks<2; ks++){
            uint32_t kOff = bufOff + ks*32;
            uint32_t af[2][4];
            #pragma unroll
            for (int mt=0;mt<2;mt++)
                ldsm4(af[mt][0], af[mt][1], af[mt][2], af[mt][3], aBase[mt] + kOff);
            uint32_t bf[8][2];
            #pragma unroll
            for (int p=0;p<4;p++)
                ldsm4(bf[2*p][0], bf[2*p][1], bf[2*p+1][0], bf[2*p+1][1], bBase[p] + kOff);
            #pragma unroll
            for (int mt=0;mt<2;mt++)
                #pragma unroll
                for (int nt=0;nt<8;nt++){
                    asm volatile(
                        "mma.sync.aligned.m16n8k16.row.col.f32.bf16.bf16.f32 "
                        "{%0,%1,%2,%3}, {%4,%5,%6,%7}, {%8,%9}, {%0,%1,%2,%3};\n"
                        : "+f"(acc[mt][nt][0]), "+f"(acc[mt][nt][1]),
                          "+f"(acc[mt][nt][2]), "+f"(acc[mt][nt][3])
                        : "r"(af[mt][0]), "r"(af[mt][1]), "r"(af[mt][2]), "r"(af[mt][3]),
                          "r"(bf[nt][0]), "r"(bf[nt][1]));
                }
        }
    }

    // Epilogue: acc[mt][nt]: rows (gid, gid+8), cols (tig*2, tig*2+1)
    #pragma unroll
    for (int mt=0;mt<2;mt++){
        int r0 = m0 + wm + mt*16 + gid;
        #pragma unroll
        for (int nt=0;nt<8;nt++){
            int c = n0 + wn + nt*8 + tig*2;
            if (c >= N) continue;
            float v[4];
            #pragma unroll
            for (int q=0;q<4;q++) v[q] = acc[mt][nt][q];
            if (EPI==1){
                #pragma unroll
                for (int q=0;q<4;q++){
                    float t = v[q] + bias[c + (q&1)];
                    v[q] = (t > 20.f) ? t : log1pf(expf(t));
                }
            }
            if (EPI==2){
                v[0] += bias[c]   + resid[(size_t)r0*ldc + c];
                v[1] += bias[c+1] + resid[(size_t)r0*ldc + c+1];
                v[2] += bias[c]   + resid[(size_t)(r0+8)*ldc + c];
                v[3] += bias[c+1] + resid[(size_t)(r0+8)*ldc + c+1];
            }
            if (sizeof(TOUT) == 4){
                *(float2*)((float*)C + (size_t)r0*ldc + c)     = make_float2(v[0], v[1]);
                *(float2*)((float*)C + (size_t)(r0+8)*ldc + c) = make_float2(v[2], v[3]);
            } else {
                *(uint32_t*)((bf16*)C + (size_t)r0*ldc + c)     = pack_bf2(v[0], v[1]);
                *(uint32_t*)((bf16*)C + (size_t)(r0+8)*ldc + c) = pack_bf2(v[2], v[3]);
            }
        }
    }
}

// ---------------- split-K reduce: 4 fp32 slabs -> bf16 -----------------------
__global__ __launch_bounds__(256) void reduce4_kernel(
    const float* __restrict__ part, bf16* __restrict__ out, int n)
{
    int i = blockIdx.x*256 + threadIdx.x;
    if (i < n){
        float s = part[i] + part[i+n] + part[i+2*n] + part[i+3*n];
        out[i] = __float2bfloat16(s);
    }
}

// ---------------- Depthwise conv + bias + SiLU, time-tiled, both dirs --------
__global__ __launch_bounds__(256) void conv2_kernel(
    const bf16* __restrict__ xz_b, const float* __restrict__ cw0,
    const float* __restrict__ cw1, const float* __restrict__ cb0,
    const float* __restrict__ cb1, bf16* __restrict__ xc_b)
{
    int dp = blockIdx.x*256 + threadIdx.x;   // 0..1023 channel pairs
    int d0 = dp*2;
    int t0 = blockIdx.y*8;
    int z = blockIdx.z;
    int dir = z >> 2, b = z & 3;
    const bf16* xz = xz_b + (size_t)dir*NM*XZW;
    bf16* xc = xc_b + (size_t)dir*NM*DI;
    const float* cw = dir ? cw1 : cw0;
    const float* cb = dir ? cb1 : cb0;
    float4 wa = *(const float4*)(cw + d0*4);
    float4 wb = *(const float4*)(cw + d0*4 + 4);
    float cba = cb[d0], cbb = cb[d0+1];
    size_t rowb = (size_t)b*LL;

    float2 vals[11];
    #pragma unroll
    for (int j=0;j<11;j++){
        int t = dir ? (t0 + j) : (t0 - 3 + j);
        if (t >= 0 && t < LL){
            uint32_t u = *(const uint32_t*)(xz + (rowb + t)*XZW + d0);
            vals[j] = unpack_bf2(u);
        } else vals[j] = make_float2(0.f, 0.f);
    }
    #pragma unroll
    for (int i=0;i<8;i++){
        float ax, ay;
        if (!dir){
            ax = cba + wa.x*vals[i].x + wa.y*vals[i+1].x + wa.z*vals[i+2].x + wa.w*vals[i+3].x;
            ay = cbb + wb.x*vals[i].y + wb.y*vals[i+1].y + wb.z*vals[i+2].y + wb.w*vals[i+3].y;
        } else {
            ax = cba + wa.w*vals[i].x + wa.z*vals[i+1].x + wa.y*vals[i+2].x + wa.x*vals[i+3].x;
            ay = cbb + wb.w*vals[i].y + wb.z*vals[i+1].y + wb.y*vals[i+2].y + wb.x*vals[i+3].y;
        }
        float sx = ax / (1.f + expf(-ax));
        float sy = ay / (1.f + expf(-ay));
        *(uint32_t*)(xc + (rowb + t0 + i)*DI + d0) = pack_bf2(sx, sy);
    }
}

// ---------------- FMA-only exp2 ----------------------------------------------
__device__ __forceinline__ float exp2p(float x){
    x = fmaxf(x, -126.f);
    float fl = floorf(x);
    float f = x - fl;
    float p = 1.5400277e-4f;
    p = fmaf(p, f, 1.3335581e-3f);
    p = fmaf(p, f, 9.6181290e-3f);
    p = fmaf(p, f, 5.5504110e-2f);
    p = fmaf(p, f, 2.4022651e-1f);
    p = fmaf(p, f, 6.9314718e-1f);
    p = fmaf(p, f, 1.0f);
    return p * __int_as_float(((int)fl + 127) << 23);
}

// ---------------- Selective scan: warp-autonomous, 4 thr/channel -------------
// 4 thr/channel (4 states each), 8 channels/warp, BC via shfl, reg prefetch.
__global__ __launch_bounds__(256) void scan2_kernel(
    const float* __restrict__ delta_b, const bf16* __restrict__ xc_b,
    const bf16* __restrict__ proj_b,  const bf16* __restrict__ xz_b,
    const float* __restrict__ A0, const float* __restrict__ A1,
    const float* __restrict__ D0, const float* __restrict__ D1,
    bf16* __restrict__ yg_b)
{
    int tid = threadIdx.x;
    int warp = tid >> 5, lane = tid & 31;
    int ch = lane >> 2, sg = lane & 3;
    int d = blockIdx.x*64 + warp*8 + ch;
    int b = blockIdx.y;
    int dir = blockIdx.z;
    const float* delta = delta_b + (size_t)dir*NM*DI;
    const bf16* xc    = xc_b    + (size_t)dir*NM*DI;
    const bf16* proj  = proj_b  + (size_t)dir*NM*PRW;
    const bf16* xz    = xz_b    + (size_t)dir*NM*XZW;
    const float* A_log = dir ? A1 : A0;
    float Dv = (dir ? D1 : D0)[d];
    bf16* yg = yg_b + (size_t)dir*NM*DI;
    const float L2E = 1.4426950408889634f;
    float c[4], h[4];
    #pragma unroll
    for (int i=0;i<4;i++){
        c[i] = -expf(A_log[(size_t)d*DS + sg*4 + i]) * L2E;
        h[i] = 0.f;
    }
    size_t rowb = (size_t)b*LL;
    int stp = dir ? -1 : 1;
    size_t m = rowb + (dir ? LL-1 : 0);
    float dlt = delta[m*DI + d];
    float xv  = __bfloat162float(xc[m*DI + d]);
    float zv  = __bfloat162float(xz[m*XZW + DI + d]);
    float bc  = __bfloat162float(proj[m*PRW + DTR + lane]);

    for (int step = 0; step < LL; step++){
        float dltn = 0.f, xvn = 0.f, zvn = 0.f, bcn = 0.f;
        if (step+1 < LL){
            size_t mn = m + stp;
            dltn = delta[mn*DI + d];
            xvn  = __bfloat162float(xc[mn*DI + d]);
            zvn  = __bfloat162float(xz[mn*XZW + DI + d]);
            bcn  = __bfloat162float(proj[mn*PRW + DTR + lane]);
        }
        float dx = dlt * xv;
        float y = 0.f;
        #pragma unroll
        for (int i=0;i<4;i++){
            float Bv = __shfl_sync(~0u, bc, sg*4 + i);
            float Cv = __shfl_sync(~0u, bc, 16 + sg*4 + i);
            float e = exp2p(dlt * c[i]);
            h[i] = fmaf(e, h[i], dx * Bv);
            y = fmaf(h[i], Cv, y);
        }
        y += __shfl_xor_sync(~0u, y, 1);
        y += __shfl_xor_sync(~0u, y, 2);
        if (sg == 0){
            float sz = zv / (1.f + expf(-zv));
            yg[m*DI + d] = __float2bfloat16((y + xv*Dv) * sz);
        }
        dlt = dltn; xv = xvn; zv = zvn; bc = bcn;
        m += stp;
    }
}

// ---------------- Host launcher ---------------------------------------------
extern "C" void kernel_launch(void* const* d_in, const int* in_sizes, int n_in,
                              void* d_out, int out_size)
{
    const float* X       = (const float*)d_in[0];
    const float* ln_g    = (const float*)d_in[1];
    const float* ln_b    = (const float*)d_in[2];
    const float* merge_w = (const float*)d_in[3];
    const float* merge_b = (const float*)d_in[4];

    bf16 *xn_p, *xz_p, *xc_p, *projbf_p, *yg_p, *ycat_p, *wbf_p;
    float *xpart_p, *delta_p;
    cudaGetSymbolAddress((void**)&xn_p,    g_xn);
    cudaGetSymbolAddress((void**)&xz_p,    g_xz);
    cudaGetSymbolAddress((void**)&xc_p,    g_xc);
    cudaGetSymbolAddress((void**)&xpart_p, g_xpart);
    cudaGetSymbolAddress((void**)&projbf_p,g_projbf);
    cudaGetSymbolAddress((void**)&delta_p, g_delta);
    cudaGetSymbolAddress((void**)&yg_p,    g_yg);
    cudaGetSymbolAddress((void**)&ycat_p,  g_ycat);
    cudaGetSymbolAddress((void**)&wbf_p,   g_wbf);

    // raise dynamic smem limit for GEMM instantiations (idempotent)
    cudaFuncSetAttribute(gemm_bf16<0,bf16>,  cudaFuncAttributeMaxDynamicSharedMemorySize, GSMEM);
    cudaFuncSetAttribute(gemm_bf16<0,float>, cudaFuncAttributeMaxDynamicSharedMemorySize, GSMEM);
    cudaFuncSetAttribute(gemm_bf16<1,float>, cudaFuncAttributeMaxDynamicSharedMemorySize, GSMEM);
    cudaFuncSetAttribute(gemm_bf16<2,float>, cudaFuncAttributeMaxDynamicSharedMemorySize, GSMEM);

    const float* W[2][9];
    for (int dir = 0; dir < 2; dir++)
        for (int i = 0; i < 9; i++)
            W[dir][i] = (const float*)d_in[5 + dir*9 + i];
    // 0 in_w, 1 conv_w, 2 conv_b, 3 xproj_w, 4 dt_w, 5 dt_b, 6 A_log, 7 D, 8 out_w

    // bf16 weight offsets (element units)
    const size_t o_in[2]   = {0, 4194304};
    const size_t o_xp[2]   = {8388608, 8585216};
    const size_t o_dtw[2]  = {8781824, 8912896};
    const size_t o_out[2]  = {9043968, 11141120};
    const size_t o_mg      = 13238272;

    // 0. convert all weights to bf16 in one launch
    cvt_all_kernel<<<(3833856+255)/256, 256>>>(
        W[0][0], W[1][0], W[0][3], W[1][3], W[0][4], W[1][4],
        W[0][8], W[1][8], merge_w, wbf_p);

    // 1. LayerNorm -> bf16
    ln_kernel<<<NM, 256>>>(X, ln_g, ln_b, xn_p);

    // 2. in-proj both dirs: [8192,4096] K=1024 -> bf16
    for (int dir = 0; dir < 2; dir++)
        gemm_bf16<0,bf16><<<dim3(XZW/128, NM/128, 1), 256, GSMEM>>>(
            xn_p, wbf_p + o_in[dir], xz_p + (size_t)dir*NM*XZW,
            NM, XZW, DM, DM, DM, XZW, 0, nullptr, nullptr);

    // 3. depthwise conv + SiLU, both dirs, time-tiled
    conv2_kernel<<<dim3(4, LL/8, 2*BB), 256>>>(
        xz_p, W[0][1], W[1][1], W[0][2], W[1][2], xc_p);

    // 4. x-proj both dirs: [8192,96] K=2048, split-K=4 -> fp32 partials
    for (int dir = 0; dir < 2; dir++)
        gemm_bf16<0,float><<<dim3(1, NM/128, 4), 256, GSMEM>>>(
            xc_p + (size_t)dir*NM*DI, wbf_p + o_xp[dir],
            xpart_p + (size_t)dir*4*NM*PRW,
            NM, PRW, 512, DI, DI, PRW, (size_t)NM*PRW, nullptr, nullptr);

    // 4b. reduce partials -> bf16 proj
    for (int dir = 0; dir < 2; dir++)
        reduce4_kernel<<<(NM*PRW+255)/256, 256>>>(
            xpart_p + (size_t)dir*4*NM*PRW, projbf_p + (size_t)dir*NM*PRW, NM*PRW);

    // 5. delta both dirs: softplus(dt @ dt_w.T + dt_b)  [8192,2048] K=64
    for (int dir = 0; dir < 2; dir++)
        gemm_bf16<1,float><<<dim3(DI/128, NM/128, 1), 256, GSMEM>>>(
            projbf_p + (size_t)dir*NM*PRW, wbf_p + o_dtw[dir], delta_p + (size_t)dir*NM*DI,
            NM, DI, DTR, PRW, DTR, DI, 0, W[dir][5], nullptr);

    // 6. selective scan + gate, both dirs
    scan2_kernel<<<dim3(DI/64, BB, 2), 256>>>(
        delta_p, xc_p, projbf_p, xz_p,
        W[0][6], W[1][6], W[0][7], W[1][7], yg_p);

    // 7. out-proj both dirs into concat buffer: [8192,1024] K=2048 -> bf16
    for (int dir = 0; dir < 2; dir++)
        gemm_bf16<0,bf16><<<dim3(DM/128, NM/128, 1), 256, GSMEM>>>(
            yg_p + (size_t)dir*NM*DI, wbf_p + o_out[dir], ycat_p + (size_t)dir*DM,
            NM, DM, DI, DI, DI, DI, 0, nullptr, nullptr);

    // 8. merge + bias + residual -> fp32 out
    gemm_bf16<2,float><<<dim3(DM/128, NM/128, 1), 256, GSMEM>>>(
        ycat_p, wbf_p + o_mg, (float*)d_out, NM, DM, DI, DI, DI, DM, 0, merge_b, X);
}

// round 8
// speedup vs baseline: 7.6308x; 1.0821x over previous
#include <cuda_runtime.h>
#include <cuda_bf16.h>
#include <cstdint>

// Problem constants
#define BB   4
#define LL   2048
#define DM   1024
#define DI   2048
#define NM   (BB*LL)      // 8192 tokens
#define XZW  4096         // per-dir 2*DI
#define XZC  8192         // concat row width (both dirs)
#define PRW  96           // dt_rank + 2*d_state
#define DTR  64
#define DS   16

typedef __nv_bfloat16 bf16;
typedef __nv_bfloat162 bf162;

// ---------------- scratch (device globals; allocation-free rule) -------------
__device__ bf16  g_xn[(size_t)NM*DM];
__device__ bf16  g_xz[(size_t)NM*XZC];          // [token, fwd_x|fwd_z|bwd_x|bwd_z]
__device__ bf16  g_xc[2][(size_t)NM*DI];
__device__ float g_xpart[2][4][(size_t)NM*PRW];
__device__ bf16  g_projbf[2][(size_t)NM*PRW];
__device__ float g_delta[2][(size_t)NM*DI];
__device__ bf16  g_yg[2][(size_t)NM*DI];
__device__ bf16  g_ycat[(size_t)NM*DI];
__device__ bf16  g_wbf[15335424];               // all weights converted to bf16

__device__ __forceinline__ uint32_t pack_bf2(float x, float y){
    bf162 h = __float22bfloat162_rn(make_float2(x, y));
    return *(uint32_t*)&h;
}
__device__ __forceinline__ float2 unpack_bf2(uint32_t u){
    bf162 h = *(bf162*)&u;
    return __bfloat1622float2(h);
}

// ---------------- fused weight fp32 -> bf16 (all 9 weights, one launch) ------
__global__ __launch_bounds__(256) void cvt_all_kernel(
    const float* __restrict__ p0, const float* __restrict__ p1,
    const float* __restrict__ p2, const float* __restrict__ p3,
    const float* __restrict__ p4, const float* __restrict__ p5,
    const float* __restrict__ p6, const float* __restrict__ p7,
    const float* __restrict__ p8, bf16* __restrict__ out)
{
    size_t i = (size_t)blockIdx.x*256 + threadIdx.x;   // quad (float4) index
    if (i >= 3833856) return;
    const size_t cum[10] = {0,1048576,2097152,2146304,2195456,2228224,
                            2260992,2785280,3309568,3833856};
    const float* ps[9] = {p0,p1,p2,p3,p4,p5,p6,p7,p8};
    int seg = 0;
    #pragma unroll
    for (int s=0; s<9; s++) if (i >= cum[s+1]) seg = s+1;
    const float4* src = (const float4*)ps[seg];
    float4 v = src[i - cum[seg]];
    ((uint2*)out)[i] = make_uint2(pack_bf2(v.x, v.y), pack_bf2(v.z, v.w));
}

// ---------------- LayerNorm (fp32 in, bf16 out) ------------------------------
__global__ __launch_bounds__(256) void ln_kernel(
    const float* __restrict__ x, const float* __restrict__ gw,
    const float* __restrict__ bw, bf16* __restrict__ xn)
{
    __shared__ float red[16];
    int m = blockIdx.x, tid = threadIdx.x;
    const float4* xr = (const float4*)(x + (size_t)m*DM);
    float4 v = xr[tid];
    float s  = v.x+v.y+v.z+v.w;
    float ss = v.x*v.x+v.y*v.y+v.z*v.z+v.w*v.w;
    #pragma unroll
    for (int o=16;o;o>>=1){ s += __shfl_xor_sync(~0u,s,o); ss += __shfl_xor_sync(~0u,ss,o); }
    if ((tid&31)==0){ red[tid>>5]=s; red[8+(tid>>5)]=ss; }
    __syncthreads();
    if (tid<32){
        float a  = (tid<8)? red[tid]   : 0.f;
        float b2 = (tid<8)? red[8+tid] : 0.f;
        #pragma unroll
        for (int o=4;o;o>>=1){ a += __shfl_xor_sync(~0u,a,o); b2 += __shfl_xor_sync(~0u,b2,o); }
        if (tid==0){ red[0]=a; red[8]=b2; }
    }
    __syncthreads();
    float mu   = red[0]*(1.0f/DM);
    float var  = red[8]*(1.0f/DM) - mu*mu;
    float rstd = rsqrtf(var + 1e-5f);
    float4 g4 = ((const float4*)gw)[tid];
    float4 b4 = ((const float4*)bw)[tid];
    uint2 o = make_uint2(
        pack_bf2((v.x-mu)*rstd*g4.x + b4.x, (v.y-mu)*rstd*g4.y + b4.y),
        pack_bf2((v.z-mu)*rstd*g4.z + b4.z, (v.w-mu)*rstd*g4.w + b4.w));
    ((uint2*)(xn + (size_t)m*DM))[tid] = o;
}

// ---------------- BF16 tensor-core GEMM, NT ----------------------------------
// 128x128x32 tile, 8 warps, m16n8k16 bf16 mma, 3-stage cp.async pipeline.
// blockIdx.z batches via explicit strides: A += z*aBatch, B += z*bBatch, C += z*cBatch.
// EPI: 0 none, 1 softplus(acc+bias), 2 acc+bias+resid.
#define BKk 32
#define SROW 20          // row stride in u32: 16 (32 bf16) + 4 pad
#define BUFU32 (128*SROW)
#define GSMEM (6*BUFU32*4)   // 3 stages x (A+B) x 10240B = 61440

__device__ __forceinline__ uint32_t smem_u32p(const void* p){
    return (uint32_t)__cvta_generic_to_shared(p);
}
__device__ __forceinline__ void ldsm4(uint32_t& r0, uint32_t& r1, uint32_t& r2, uint32_t& r3, uint32_t a){
    asm volatile("ldmatrix.sync.aligned.m8n8.x4.shared.b16 {%0,%1,%2,%3}, [%4];\n"
        : "=r"(r0), "=r"(r1), "=r"(r2), "=r"(r3) : "r"(a));
}
__device__ __forceinline__ void cp_async16(uint32_t dst, const void* src, int srcsize){
    asm volatile("cp.async.cg.shared.global [%0], [%1], 16, %2;\n"
        :: "r"(dst), "l"(src), "r"(srcsize));
}

template<int EPI, typename TOUT>
__global__ __launch_bounds__(256, 2) void gemm_bf16(
    const bf16* __restrict__ A, const bf16* __restrict__ B, TOUT* __restrict__ C,
    int M, int N, int K, int lda, int ldb, int ldc,
    size_t aBatch, size_t bBatch, size_t cBatch,
    const float* __restrict__ bias, const float* __restrict__ resid)
{
    extern __shared__ uint32_t sm[];
    uint32_t* As = sm;               // 3*BUFU32
    uint32_t* Bs = sm + 3*BUFU32;    // 3*BUFU32

    A += (size_t)blockIdx.z * aBatch;
    B += (size_t)blockIdx.z * bBatch;
    C += (size_t)blockIdx.z * cBatch;

    int tid  = threadIdx.x;
    int warp = tid >> 5, lane = tid & 31;
    int gid  = lane >> 2, tig = lane & 3;
    int wm   = (warp >> 1) * 32;
    int wn   = (warp & 1) * 64;
    int m0 = blockIdx.y * 128, n0 = blockIdx.x * 128;

    // staging: slot s (0..511): row = s>>2, seg = s&3 (16B segment)
    int srow[2], sseg[2];
    #pragma unroll
    for (int i=0;i<2;i++){ int s = tid + i*256; srow[i] = s>>2; sseg[i] = s&3; }

    auto issue = [&](int buf, int k0){
        uint32_t* Ab = As + buf*BUFU32;
        uint32_t* Bb = Bs + buf*BUFU32;
        #pragma unroll
        for (int i=0;i<2;i++){
            const bf16* sa = A + (size_t)(m0+srow[i])*lda + k0 + sseg[i]*8;
            cp_async16(smem_u32p(Ab + srow[i]*SROW + sseg[i]*4), sa, 16);
            int nrow = n0 + srow[i];
            const bf16* sb = B + (size_t)nrow*ldb + k0 + sseg[i]*8;
            cp_async16(smem_u32p(Bb + srow[i]*SROW + sseg[i]*4), sb, (nrow<N)?16:0);
        }
        asm volatile("cp.async.commit_group;\n" ::: "memory");
    };

    int g = lane >> 3, r = lane & 7;
    uint32_t aBase[2], bBase[4];
    #pragma unroll
    for (int mt=0;mt<2;mt++)
        aBase[mt] = smem_u32p(&As[(wm + mt*16 + (g&1)*8 + r)*SROW + (g>>1)*4]);
    #pragma unroll
    for (int p=0;p<4;p++)
        bBase[p] = smem_u32p(&Bs[(wn + p*16 + (g>>1)*8 + r)*SROW + (g&1)*4]);

    float acc[2][8][4];
    #pragma unroll
    for (int mt=0;mt<2;mt++)
        #pragma unroll
        for (int nt=0;nt<8;nt++)
            #pragma unroll
            for (int q=0;q<4;q++) acc[mt][nt][q]=0.f;

    int nchunk = K / BKk;
    issue(0, 0);
    if (nchunk > 1) issue(1, BKk);

    for (int ck=0; ck<nchunk; ck++){
        if (ck+1 < nchunk) asm volatile("cp.async.wait_group 1;\n" ::: "memory");
        else               asm volatile("cp.async.wait_group 0;\n" ::: "memory");
        __syncthreads();
        if (ck+2 < nchunk) issue((ck+2)%3, (ck+2)*BKk);

        uint32_t bufOff = (uint32_t)(ck%3) * (BUFU32*4);
        #pragma unroll
        for (int ks=0; ks<2; ks++){
            uint32_t kOff = bufOff + ks*32;
            uint32_t af[2][4];
            #pragma unroll
            for (int mt=0;mt<2;mt++)
                ldsm4(af[mt][0], af[mt][1], af[mt][2], af[mt][3], aBase[mt] + kOff);
            uint32_t bf[8][2];
            #pragma unroll
            for (int p=0;p<4;p++)
                ldsm4(bf[2*p][0], bf[2*p][1], bf[2*p+1][0], bf[2*p+1][1], bBase[p] + kOff);
            #pragma unroll
            for (int mt=0;mt<2;mt++)
                #pragma unroll
                for (int nt=0;nt<8;nt++){
                    asm volatile(
                        "mma.sync.aligned.m16n8k16.row.col.f32.bf16.bf16.f32 "
                        "{%0,%1,%2,%3}, {%4,%5,%6,%7}, {%8,%9}, {%0,%1,%2,%3};\n"
                        : "+f"(acc[mt][nt][0]), "+f"(acc[mt][nt][1]),
                          "+f"(acc[mt][nt][2]), "+f"(acc[mt][nt][3])
                        : "r"(af[mt][0]), "r"(af[mt][1]), "r"(af[mt][2]), "r"(af[mt][3]),
                          "r"(bf[nt][0]), "r"(bf[nt][1]));
                }
        }
    }

    // Epilogue: acc[mt][nt]: rows (gid, gid+8), cols (tig*2, tig*2+1)
    #pragma unroll
    for (int mt=0;mt<2;mt++){
        int r0 = m0 + wm + mt*16 + gid;
        #pragma unroll
        for (int nt=0;nt<8;nt++){
            int c = n0 + wn + nt*8 + tig*2;
            if (c >= N) continue;
            float v[4];
            #pragma unroll
            for (int q=0;q<4;q++) v[q] = acc[mt][nt][q];
            if (EPI==1){
                #pragma unroll
                for (int q=0;q<4;q++){
                    float t = v[q] + bias[c + (q&1)];
                    v[q] = (t > 20.f) ? t : log1pf(expf(t));
                }
            }
            if (EPI==2){
                v[0] += bias[c]   + resid[(size_t)r0*ldc + c];
                v[1] += bias[c+1] + resid[(size_t)r0*ldc + c+1];
                v[2] += bias[c]   + resid[(size_t)(r0+8)*ldc + c];
                v[3] += bias[c+1] + resid[(size_t)(r0+8)*ldc + c+1];
            }
            if (sizeof(TOUT) == 4){
                *(float2*)((float*)C + (size_t)r0*ldc + c)     = make_float2(v[0], v[1]);
                *(float2*)((float*)C + (size_t)(r0+8)*ldc + c) = make_float2(v[2], v[3]);
            } else {
                *(uint32_t*)((bf16*)C + (size_t)r0*ldc + c)     = pack_bf2(v[0], v[1]);
                *(uint32_t*)((bf16*)C + (size_t)(r0+8)*ldc + c) = pack_bf2(v[2], v[3]);
            }
        }
    }
}

// ---------------- split-K reduce: 4 fp32 slabs -> bf16 -----------------------
__global__ __launch_bounds__(256) void reduce4_kernel(
    const float* __restrict__ part, bf16* __restrict__ out, int n)
{
    int i = blockIdx.x*256 + threadIdx.x;
    if (i < n){
        float s = part[i] + part[i+n] + part[i+2*n] + part[i+3*n];
        out[i] = __float2bfloat16(s);
    }
}

// ---------------- Depthwise conv + bias + SiLU, time-tiled, both dirs --------
// xz is the concat buffer [NM, XZC]; x part at dir*XZW + d.
__global__ __launch_bounds__(256) void conv2_kernel(
    const bf16* __restrict__ xz, const float* __restrict__ cw0,
    const float* __restrict__ cw1, const float* __restrict__ cb0,
    const float* __restrict__ cb1, bf16* __restrict__ xc_b)
{
    int dp = blockIdx.x*256 + threadIdx.x;   // 0..1023 channel pairs
    int d0 = dp*2;
    int t0 = blockIdx.y*8;
    int z = blockIdx.z;
    int dir = z >> 2, b = z & 3;
    bf16* xc = xc_b + (size_t)dir*NM*DI;
    const float* cw = dir ? cw1 : cw0;
    const float* cb = dir ? cb1 : cb0;
    float4 wa = *(const float4*)(cw + d0*4);
    float4 wb = *(const float4*)(cw + d0*4 + 4);
    float cba = cb[d0], cbb = cb[d0+1];
    size_t rowb = (size_t)b*LL;
    size_t coff = (size_t)dir*XZW + d0;

    float2 vals[11];
    #pragma unroll
    for (int j=0;j<11;j++){
        int t = dir ? (t0 + j) : (t0 - 3 + j);
        if (t >= 0 && t < LL){
            uint32_t u = *(const uint32_t*)(xz + (rowb + t)*XZC + coff);
            vals[j] = unpack_bf2(u);
        } else vals[j] = make_float2(0.f, 0.f);
    }
    #pragma unroll
    for (int i=0;i<8;i++){
        float ax, ay;
        if (!dir){
            ax = cba + wa.x*vals[i].x + wa.y*vals[i+1].x + wa.z*vals[i+2].x + wa.w*vals[i+3].x;
            ay = cbb + wb.x*vals[i].y + wb.y*vals[i+1].y + wb.z*vals[i+2].y + wb.w*vals[i+3].y;
        } else {
            ax = cba + wa.w*vals[i].x + wa.z*vals[i+1].x + wa.y*vals[i+2].x + wa.x*vals[i+3].x;
            ay = cbb + wb.w*vals[i].y + wb.z*vals[i+1].y + wb.y*vals[i+2].y + wb.x*vals[i+3].y;
        }
        float sx = ax / (1.f + expf(-ax));
        float sy = ay / (1.f + expf(-ay));
        *(uint32_t*)(xc + (rowb + t0 + i)*DI + d0) = pack_bf2(sx, sy);
    }
}

// ---------------- FMA-only exp2 ----------------------------------------------
__device__ __forceinline__ float exp2p(float x){
    x = fmaxf(x, -126.f);
    float fl = floorf(x);
    float f = x - fl;
    float p = 1.5400277e-4f;
    p = fmaf(p, f, 1.3335581e-3f);
    p = fmaf(p, f, 9.6181290e-3f);
    p = fmaf(p, f, 5.5504110e-2f);
    p = fmaf(p, f, 2.4022651e-1f);
    p = fmaf(p, f, 6.9314718e-1f);
    p = fmaf(p, f, 1.0f);
    return p * __int_as_float(((int)fl + 127) << 23);
}

// ---------------- Selective scan: 8-deep register pipeline -------------------
// 4 thr/channel (4 states each), 8 channels/warp, BC via shfl.
// Time unrolled x8 with two named register blocks (A/B) -> MLP ~32.
#define SU 8
__global__ __launch_bounds__(256) void scan2_kernel(
    const float* __restrict__ delta_b, const bf16* __restrict__ xc_b,
    const bf16* __restrict__ proj_b,  const bf16* __restrict__ xz,
    const float* __restrict__ A0, const float* __restrict__ A1,
    const float* __restrict__ D0, const float* __restrict__ D1,
    bf16* __restrict__ yg_b)
{
    int tid = threadIdx.x;
    int warp = tid >> 5, lane = tid & 31;
    int ch = lane >> 2, sg = lane & 3;
    int d = blockIdx.x*64 + warp*8 + ch;
    int b = blockIdx.y;
    int dir = blockIdx.z;
    const float* delta = delta_b + (size_t)dir*NM*DI;
    const bf16* xc    = xc_b    + (size_t)dir*NM*DI;
    const bf16* proj  = proj_b  + (size_t)dir*NM*PRW;
    const float* A_log = dir ? A1 : A0;
    float Dv = (dir ? D1 : D0)[d];
    bf16* yg = yg_b + (size_t)dir*NM*DI;
    const float L2E = 1.4426950408889634f;
    float c[4], h[4];
    #pragma unroll
    for (int i=0;i<4;i++){
        c[i] = -expf(A_log[(size_t)d*DS + sg*4 + i]) * L2E;
        h[i] = 0.f;
    }
    size_t rowb = (size_t)b*LL;
    size_t zoff = (size_t)dir*XZW + DI + d;   // z-gate column in concat xz

    float Ad[SU], Ax[SU], Az[SU], Ab[SU];
    float Bd[SU], Bx[SU], Bz[SU], Bb[SU];

    auto loadblk = [&](int blk, float* pd, float* px, float* pz, float* pb){
        #pragma unroll
        for (int j=0;j<SU;j++){
            int t = blk + j;
            size_t mm = rowb + (dir ? (LL-1-t) : t);
            pd[j] = delta[mm*DI + d];
            px[j] = __bfloat162float(xc[mm*DI + d]);
            pz[j] = __bfloat162float(xz[mm*XZC + zoff]);
            pb[j] = __bfloat162float(proj[mm*PRW + DTR + lane]);
        }
    };
    auto compute = [&](int blk, float* pd, float* px, float* pz, float* pb){
        #pragma unroll
        for (int j=0;j<SU;j++){
            float dlt = pd[j], xv = px[j];
            float dx = dlt * xv;
            float y = 0.f;
            #pragma unroll
            for (int i=0;i<4;i++){
                float Bv = __shfl_sync(~0u, pb[j], sg*4 + i);
                float Cv = __shfl_sync(~0u, pb[j], 16 + sg*4 + i);
                float e = exp2p(dlt * c[i]);
                h[i] = fmaf(e, h[i], dx * Bv);
                y = fmaf(h[i], Cv, y);
            }
            y += __shfl_xor_sync(~0u, y, 1);
            y += __shfl_xor_sync(~0u, y, 2);
            if (sg == 0){
                float zv = pz[j];
                float sz = zv / (1.f + expf(-zv));
                int t = blk + j;
                size_t mm = rowb + (dir ? (LL-1-t) : t);
                yg[mm*DI + d] = __float2bfloat16((y + xv*Dv) * sz);
            }
        }
    };

    loadblk(0, Ad, Ax, Az, Ab);
    for (int blk = 0; blk < LL; blk += 2*SU){
        if (blk + SU < LL) loadblk(blk + SU, Bd, Bx, Bz, Bb);
        compute(blk, Ad, Ax, Az, Ab);
        if (blk + 2*SU < LL) loadblk(blk + 2*SU, Ad, Ax, Az, Ab);
        if (blk + SU < LL) compute(blk + SU, Bd, Bx, Bz, Bb);
    }
}

// ---------------- Host launcher ---------------------------------------------
extern "C" void kernel_launch(void* const* d_in, const int* in_sizes, int n_in,
                              void* d_out, int out_size)
{
    const float* X       = (const float*)d_in[0];
    const float* ln_g    = (const float*)d_in[1];
    const float* ln_b    = (const float*)d_in[2];
    const float* merge_w = (const float*)d_in[3];
    const float* merge_b = (const float*)d_in[4];

    bf16 *xn_p, *xz_p, *xc_p, *projbf_p, *yg_p, *ycat_p, *wbf_p;
    float *xpart_p, *delta_p;
    cudaGetSymbolAddress((void**)&xn_p,    g_xn);
    cudaGetSymbolAddress((void**)&xz_p,    g_xz);
    cudaGetSymbolAddress((void**)&xc_p,    g_xc);
    cudaGetSymbolAddress((void**)&xpart_p, g_xpart);
    cudaGetSymbolAddress((void**)&projbf_p,g_projbf);
    cudaGetSymbolAddress((void**)&delta_p, g_delta);
    cudaGetSymbolAddress((void**)&yg_p,    g_yg);
    cudaGetSymbolAddress((void**)&ycat_p,  g_ycat);
    cudaGetSymbolAddress((void**)&wbf_p,   g_wbf);

    cudaFuncSetAttribute(gemm_bf16<0,bf16>,  cudaFuncAttributeMaxDynamicSharedMemorySize, GSMEM);
    cudaFuncSetAttribute(gemm_bf16<0,float>, cudaFuncAttributeMaxDynamicSharedMemorySize, GSMEM);
    cudaFuncSetAttribute(gemm_bf16<1,float>, cudaFuncAttributeMaxDynamicSharedMemorySize, GSMEM);
    cudaFuncSetAttribute(gemm_bf16<2,float>, cudaFuncAttributeMaxDynamicSharedMemorySize, GSMEM);

    const float* W[2][9];
    for (int dir = 0; dir < 2; dir++)
        for (int i = 0; i < 9; i++)
            W[dir][i] = (const float*)d_in[5 + dir*9 + i];
    // 0 in_w, 1 conv_w, 2 conv_b, 3 xproj_w, 4 dt_w, 5 dt_b, 6 A_log, 7 D, 8 out_w

    // bf16 weight offsets (element units)
    const size_t o_in   = 0;                 // fwd in_w then bwd in_w (8192x1024)
    const size_t o_xp[2]  = {8388608, 8585216};
    const size_t o_dtw[2] = {8781824, 8912896};
    const size_t o_out[2] = {9043968, 11141120};
    const size_t o_mg     = 13238272;

    // 0. convert all weights to bf16 in one launch
    cvt_all_kernel<<<(3833856+255)/256, 256>>>(
        W[0][0], W[1][0], W[0][3], W[1][3], W[0][4], W[1][4],
        W[0][8], W[1][8], merge_w, wbf_p);

    // 1. LayerNorm -> bf16
    ln_kernel<<<NM, 256>>>(X, ln_g, ln_b, xn_p);

    // 2. in-proj BOTH dirs in one GEMM: [8192, 8192] K=1024 -> bf16 concat
    gemm_bf16<0,bf16><<<dim3(XZC/128, NM/128, 1), 256, GSMEM>>>(
        xn_p, wbf_p + o_in, xz_p,
        NM, XZC, DM, DM, DM, XZC, 0, 0, 0, nullptr, nullptr);

    // 3. depthwise conv + SiLU, both dirs, time-tiled
    conv2_kernel<<<dim3(4, LL/8, 2*BB), 256>>>(
        xz_p, W[0][1], W[1][1], W[0][2], W[1][2], xc_p);

    // 4. x-proj both dirs: [8192,96] K=2048, split-K=4 -> fp32 partials
    for (int dir = 0; dir < 2; dir++)
        gemm_bf16<0,float><<<dim3(1, NM/128, 4), 256, GSMEM>>>(
            xc_p + (size_t)dir*NM*DI, wbf_p + o_xp[dir],
            xpart_p + (size_t)dir*4*NM*PRW,
            NM, PRW, 512, DI, DI, PRW, 512, 512, (size_t)NM*PRW, nullptr, nullptr);

    // 4b. reduce partials -> bf16 proj
    for (int dir = 0; dir < 2; dir++)
        reduce4_kernel<<<(NM*PRW+255)/256, 256>>>(
            xpart_p + (size_t)dir*4*NM*PRW, projbf_p + (size_t)dir*NM*PRW, NM*PRW);

    // 5. delta both dirs: softplus(dt @ dt_w.T + dt_b)  [8192,2048] K=64
    for (int dir = 0; dir < 2; dir++)
        gemm_bf16<1,float><<<dim3(DI/128, NM/128, 1), 256, GSMEM>>>(
            projbf_p + (size_t)dir*NM*PRW, wbf_p + o_dtw[dir], delta_p + (size_t)dir*NM*DI,
            NM, DI, DTR, PRW, DTR, DI, 0, 0, 0, W[dir][5], nullptr);

    // 6. selective scan + gate, both dirs, deep-prefetch
    scan2_kernel<<<dim3(DI/64, BB, 2), 256>>>(
        delta_p, xc_p, projbf_p, xz_p,
        W[0][6], W[1][6], W[0][7], W[1][7], yg_p);

    // 7. out-proj BOTH dirs batched via grid.z: [8192,1024] K=2048 -> bf16 concat
    gemm_bf16<0,bf16><<<dim3(DM/128, NM/128, 2), 256, GSMEM>>>(
        yg_p, wbf_p + o_out[0], ycat_p,
        NM, DM, DI, DI, DI, DI,
        (size_t)NM*DI, o_out[1]-o_out[0], (size_t)DM, nullptr, nullptr);

    // 8. merge + bias + residual -> fp32 out
    gemm_bf16<2,float><<<dim3(DM/128, NM/128, 1), 256, GSMEM>>>(
        ycat_p, wbf_p + o_mg, (float*)d_out, NM, DM, DI, DI, DI, DM, 0, 0, 0, merge_b, X);
}